// round 9
// baseline (speedup 1.0000x reference)
#include <cuda_runtime.h>
#include <math.h>

#define NB 64
#define CC 64
#define TT 256
#define VV 25
#define SS 3
#define II 16

typedef unsigned long long ull;

// ---------------- device scratch ----------------
__device__ float g_A1 [NB*SS*VV*VV];
__device__ float g_Ai [NB*SS*VV*VV];
__device__ float g_y0 [NB*CC*TT*VV];   // ~105MB
__device__ float g_ST [NB*CC*VV];
__device__ float g_SVw[NB*CC*TT];
__device__ float g_gs [NB*VV];
__device__ float g_gt [NB*TT];
__device__ float g_gc [NB*CC];

__device__ __forceinline__ float sigm(float x) { return 1.0f / (1.0f + expf(-x)); }

// packed fp32x2 helpers
__device__ __forceinline__ ull pack2(float f) {
    ull r;
    asm("mov.b64 %0, {%1, %1};" : "=l"(r) : "r"(__float_as_uint(f)));
    return r;
}
__device__ __forceinline__ void fma2(ull& d, ull a, ull b) {
    asm("fma.rn.f32x2 %0, %1, %2, %0;" : "+l"(d) : "l"(a), "l"(b));
}
__device__ __forceinline__ float2 unpack2(ull p) {
    unsigned lo, hi;
    asm("mov.b64 {%0, %1}, %2;" : "=r"(lo), "=r"(hi) : "l"(p));
    return make_float2(__uint_as_float(lo), __uint_as_float(hi));
}

// ---------------- K0 ----------------
__global__ void k0_zero() {
    const int tot = NB*SS*VV*VV + NB*CC*VV;
    for (int i = blockIdx.x*blockDim.x + threadIdx.x; i < tot; i += gridDim.x*blockDim.x) {
        if (i < NB*SS*VV*VV) g_A1[i] = 0.f;
        else                 g_ST[i - NB*SS*VV*VV] = 0.f;
    }
}

// ---------------- K1: embeddings + partial A1 ----------------
// grid (8, 64), 256 threads, dyn smem 67968 B
__global__ __launch_bounds__(256) void k1_emb_adj(
    const float* __restrict__ x,  const float* __restrict__ Wa, const float* __restrict__ ba,
    const float* __restrict__ Wb, const float* __restrict__ bb)
{
    extern __shared__ float sm1[];
    float* Xs  = sm1;             // 6400
    float* Es  = sm1 + 6400;      // 3584: 32 x 112, flat [0,100) per row
    float* Wt3 = sm1 + 9984;      // 6912: [s][c][36-pad j]
    float* bs3 = sm1 + 16896;     // 96

    const int tid = threadIdx.x;
    const int n   = blockIdx.y;

    for (int i = tid; i < 6144; i += 256) {
        int s = i >> 11, r = i & 2047, j = r >> 6, c = r & 63;
        float w = (j < 16) ? Wa[(s*16 + j)*64 + c] : Wb[(s*16 + (j-16))*64 + c];
        Wt3[(s*64 + c)*36 + j] = w;
    }
    if (tid < 96) {
        int s = tid / 32, j = tid % 32;
        bs3[tid] = (j < 16) ? ba[s*16 + j] : bb[s*16 + (j-16)];
    }

    float accA0[SS], accA1[SS], accA2[SS], accA3[SS];
    #pragma unroll
    for (int s = 0; s < SS; ++s) { accA0[s]=0.f; accA1[s]=0.f; accA2[s]=0.f; accA3[s]=0.f; }
    const bool hasA = tid < 175;
    const int  vA = tid / 7, w4A = tid % 7;
    const bool hasE = tid < 200;
    const int  jg = tid / 25, q = tid % 25;

    __syncthreads();

    for (int sub = 0; sub < 8; ++sub) {
        const int tile = blockIdx.x * 8 + sub;
        __syncthreads();
        {
            const float4* xg = (const float4*)x;
            float4* Xs4 = (float4*)Xs;
            for (int i = tid; i < 1600; i += 256) {
                int c = i / 25, qq = i - c*25;
                Xs4[c*25 + qq] = xg[(n*64 + c)*1600 + tile*25 + qq];
            }
        }
        __syncthreads();

        for (int s = 0; s < SS; ++s) {
            if (hasE) {
                const ulonglong2* Xs2 = (const ulonglong2*)Xs;
                const float* wb_ = Wt3 + s*64*36;
                const float* bsp = bs3 + s*32 + jg*4;
                ull a0x = pack2(bsp[0]), a0y = a0x;
                ull a1x = pack2(bsp[1]), a1y = a1x;
                ull a2x = pack2(bsp[2]), a2y = a2x;
                ull a3x = pack2(bsp[3]), a3y = a3x;
                #pragma unroll 8
                for (int c = 0; c < 64; ++c) {
                    float4 wv = *(const float4*)(wb_ + c*36 + jg*4);
                    ulonglong2 xv = Xs2[c*25 + q];
                    ull w0 = pack2(wv.x), w1 = pack2(wv.y), w2 = pack2(wv.z), w3 = pack2(wv.w);
                    fma2(a0x, w0, xv.x); fma2(a0y, w0, xv.y);
                    fma2(a1x, w1, xv.x); fma2(a1y, w1, xv.y);
                    fma2(a2x, w2, xv.x); fma2(a2y, w2, xv.y);
                    fma2(a3x, w3, xv.x); fma2(a3y, w3, xv.y);
                }
                ulonglong2* Es2 = (ulonglong2*)Es;
                Es2[(jg*4+0)*28 + q] = make_ulonglong2(a0x, a0y);
                Es2[(jg*4+1)*28 + q] = make_ulonglong2(a1x, a1y);
                Es2[(jg*4+2)*28 + q] = make_ulonglong2(a2x, a2y);
                Es2[(jg*4+3)*28 + q] = make_ulonglong2(a3x, a3y);
            }
            __syncthreads();

            if (hasA) {
                float c0 = accA0[s], c1 = accA1[s], c2 = accA2[s], c3 = accA3[s];
                #pragma unroll 4
                for (int j = 0; j < 16; ++j) {
                    #pragma unroll
                    for (int t = 0; t < 4; ++t) {
                        float av = Es[j*112 + t*25 + vA];
                        const float* br = &Es[(16+j)*112 + t*25 + w4A*4];
                        c0 += av*br[0]; c1 += av*br[1]; c2 += av*br[2]; c3 += av*br[3];
                    }
                }
                accA0[s] = c0; accA1[s] = c1; accA2[s] = c2; accA3[s] = c3;
            }
            __syncthreads();
        }
    }

    if (hasA) {
        #pragma unroll
        for (int s = 0; s < SS; ++s) {
            float* dst = &g_A1[((n*SS + s)*VV + vA)*VV];
            float vals[4] = {accA0[s], accA1[s], accA2[s], accA3[s]};
            #pragma unroll
            for (int k = 0; k < 4; ++k) {
                int w = w4A*4 + k;
                if (w < VV) atomicAdd(&dst[w], vals[k]);
            }
        }
    }
}

// ---------------- K2 ----------------
__global__ void k2_adj(const float* __restrict__ PA, const float* __restrict__ alpha) {
    const float al = alpha[0];
    const int tot = NB*SS*VV*VV;
    for (int i = blockIdx.x*blockDim.x + threadIdx.x; i < tot; i += gridDim.x*blockDim.x)
        g_Ai[i] = PA[i % (SS*VV*VV)] + al * tanhf(g_A1[i] * (1.0f/4096.0f));
}

// ---------------- K3: main fused compute (256 threads for occupancy) ----------------
// grid (64, 64), 256 threads, dyn smem 48896 B -> 3 blocks/SM, 24 warps
__global__ __launch_bounds__(256, 3) void k3_main(
    const float* __restrict__ x,  const float* __restrict__ Wd, const float* __restrict__ bd,
    const float* __restrict__ gamma, const float* __restrict__ beta)
{
    extern __shared__ float sm[];
    float* Zs  = sm;            // 7168: [64][112]
    float* Ais = sm + 7168;     // 704:  [25][28]
    float* Wds = sm + 7872;     // 4352: [c][68-pad o]  (Wd transposed)

    const int tid  = threadIdx.x;
    const int n    = blockIdx.y;
    const int tile = blockIdx.x;                  // t0 = tile*4
    // Z-stage: one (c,t) row per thread
    const int cz = tid >> 2, tz = tid & 3;
    // GEMM: 2 o's x w-half per thread
    const int o2 = tid >> 3;                      // 0..31
    const int th = (tid >> 2) & 1;                // w-half: 0 -> [0,16), 1 -> [16,28)
    const int tq = tid & 3;
    const int o0 = o2*2, o1 = o0 + 1;
    const int wb = th*16;

    if (tid < 25) { Ais[tid*28+25] = 0.f; Ais[tid*28+26] = 0.f; Ais[tid*28+27] = 0.f; }

    ull accA[8], accB[8];
    #pragma unroll
    for (int k = 0; k < 8; ++k) { accA[k] = 0ULL; accB[k] = 0ULL; }

    for (int s = 0; s < SS; ++s) {
        __syncthreads();
        for (int i = tid; i < 625; i += 256) Ais[(i/25)*28 + (i%25)] = g_Ai[(n*SS + s)*625 + i];
        for (int i = tid; i < 4096; i += 256) {
            int o = i >> 6, c = i & 63;
            Wds[c*68 + o] = Wd[s*4096 + i];
        }
        __syncthreads();

        // Z[c][t][w] = sum_v X[c][t][v] * Ai[v][w] — one row per thread
        {
            const float* xp = x + (n*64 + cz)*6400 + (tile*4 + tz)*25;
            float xr[25];
            #pragma unroll
            for (int v = 0; v < 25; ++v) xr[v] = xp[v];
            const ulonglong2* Ai2 = (const ulonglong2*)Ais;
            ull z[14];
            #pragma unroll
            for (int k = 0; k < 14; ++k) z[k] = 0ULL;
            #pragma unroll
            for (int v = 0; v < 25; ++v) {
                ull xv = pack2(xr[v]);
                #pragma unroll
                for (int w4 = 0; w4 < 7; ++w4) {
                    ulonglong2 a = Ai2[v*7 + w4];
                    fma2(z[2*w4], xv, a.x); fma2(z[2*w4+1], xv, a.y);
                }
            }
            ulonglong2* zd = (ulonglong2*)(Zs + cz*112 + tz*28);
            #pragma unroll
            for (int w4 = 0; w4 < 7; ++w4) zd[w4] = make_ulonglong2(z[2*w4], z[2*w4+1]);
        }
        __syncthreads();

        // Y[o][t][w] += sum_c W[o][c] * Z[c][t][w]
        if (th == 0) {
            #pragma unroll 4
            for (int c = 0; c < 64; ++c) {
                float2 wv = *(const float2*)(Wds + c*68 + o0);
                ull wa = pack2(wv.x), wbk = pack2(wv.y);
                const ulonglong2* zp = (const ulonglong2*)(Zs + c*112 + tq*28);
                ulonglong2 q0 = zp[0], q1 = zp[1], q2 = zp[2], q3 = zp[3];
                fma2(accA[0], wa, q0.x); fma2(accA[1], wa, q0.y);
                fma2(accA[2], wa, q1.x); fma2(accA[3], wa, q1.y);
                fma2(accA[4], wa, q2.x); fma2(accA[5], wa, q2.y);
                fma2(accA[6], wa, q3.x); fma2(accA[7], wa, q3.y);
                fma2(accB[0], wbk, q0.x); fma2(accB[1], wbk, q0.y);
                fma2(accB[2], wbk, q1.x); fma2(accB[3], wbk, q1.y);
                fma2(accB[4], wbk, q2.x); fma2(accB[5], wbk, q2.y);
                fma2(accB[6], wbk, q3.x); fma2(accB[7], wbk, q3.y);
            }
        } else {
            #pragma unroll 4
            for (int c = 0; c < 64; ++c) {
                float2 wv = *(const float2*)(Wds + c*68 + o0);
                ull wa = pack2(wv.x), wbk = pack2(wv.y);
                const ulonglong2* zp = (const ulonglong2*)(Zs + c*112 + tq*28 + 16);
                ulonglong2 q0 = zp[0], q1 = zp[1], q2 = zp[2];
                fma2(accA[0], wa, q0.x); fma2(accA[1], wa, q0.y);
                fma2(accA[2], wa, q1.x); fma2(accA[3], wa, q1.y);
                fma2(accA[4], wa, q2.x); fma2(accA[5], wa, q2.y);
                fma2(accB[0], wbk, q0.x); fma2(accB[1], wbk, q0.y);
                fma2(accB[2], wbk, q1.x); fma2(accB[3], wbk, q1.y);
                fma2(accB[4], wbk, q2.x); fma2(accB[5], wbk, q2.y);
            }
        }
    }
    __syncthreads();   // all Zs reads done

    // epilogue: bias + BN + residual + relu; stage y0 into Zs flat [o][t*25+w]
    {
        const float scl = rsqrtf(1.0f + 1e-5f);
        const int cnt = th ? 9 : 16;   // real w's in this half (w < 25)
        #pragma unroll
        for (int k = 0; k < 2; ++k) {
            const int o = (k == 0) ? o0 : o1;
            const ull* ac = (k == 0) ? accA : accB;
            const float bsum = bd[o] + bd[64+o] + bd[128+o];
            const float scv  = gamma[o]*scl;
            const float btv  = beta[o];
            const float* xp = x + (n*64 + o)*6400 + (tile*4 + tq)*25 + wb;
            float* zsp = Zs + o*100 + tq*25 + wb;
            float yv[16];
            #pragma unroll
            for (int u = 0; u < 8; ++u) {
                float2 f = unpack2(ac[u]); yv[2*u] = f.x; yv[2*u+1] = f.y;
            }
            for (int j = 0; j < cnt; ++j)
                zsp[j] = fmaxf((yv[j] + bsum)*scv + btv + xp[j], 0.f);
        }
    }
    __syncthreads();

    {   // coalesced y0 store + ST atomic accumulate
        float4* yg = (float4*)g_y0;
        const float4* Zs4 = (const float4*)Zs;
        for (int i = tid; i < 1600; i += 256) {
            int c = i / 25, qq = i - c*25;
            yg[(n*64 + c)*1600 + tile*25 + qq] = Zs4[c*25 + qq];
        }
        for (int i = tid; i < 1600; i += 256) {
            int c = i / 25, v = i - c*25;
            float ssum = Zs[c*100 + v] + Zs[c*100 + 25 + v]
                       + Zs[c*100 + 50 + v] + Zs[c*100 + 75 + v];
            atomicAdd(&g_ST[n*1600 + i], ssum);
        }
    }
}

// ---------------- K4: spatial gate ----------------
__global__ __launch_bounds__(128) void k4_sgate(const float* __restrict__ Wsa,
                                                const float* __restrict__ bsa)
{
    __shared__ float se[1600];
    __shared__ float wk[1600];
    const int tid = threadIdx.x, n = blockIdx.x;
    for (int i = tid; i < 1600; i += 128) {
        se[i] = g_ST[n*1600 + i] * (1.0f/256.0f);
        wk[i] = Wsa[i];
    }
    __syncthreads();
    if (tid < VV) {
        int v = tid;
        float acc = bsa[0];
        for (int c = 0; c < 64; ++c)
            #pragma unroll
            for (int k = 0; k < 25; ++k) {
                int u = v + k - 12;
                if (u >= 0 && u < 25) acc += wk[c*25 + k] * se[c*25 + u];
            }
        g_gs[n*25 + v] = 1.0f + sigm(acc);
    }
}

// ---------------- K5: SVw = sum_v y0*(1+gs) ----------------
__global__ __launch_bounds__(256) void k5_svw() {
    __shared__ float gs[25];
    const int c = blockIdx.x, n = blockIdx.y, t = threadIdx.x;
    if (t < 25) gs[t] = g_gs[n*25 + t];
    __syncthreads();
    const float* row = &g_y0[((n*64 + c)*256 + t)*25];
    float s = 0.f;
    #pragma unroll
    for (int v = 0; v < 25; ++v) s += row[v] * gs[v];
    g_SVw[(n*64 + c)*256 + t] = s;
}

// ---------------- K6: temporal gate ----------------
__global__ __launch_bounds__(256) void k6_tgate(const float* __restrict__ Wta,
                                                const float* __restrict__ bta)
{
    __shared__ float wk[576];
    const int tid = threadIdx.x, n = blockIdx.x;
    for (int i = tid; i < 576; i += 256) wk[i] = Wta[i];
    __syncthreads();
    const int t = tid;
    float s = 0.f;
    for (int c = 0; c < 64; ++c) {
        const float* sv = &g_SVw[(n*64 + c)*256];
        #pragma unroll
        for (int k = 0; k < 9; ++k) {
            int u = t + k - 4;
            if (u >= 0 && u < 256) s += wk[c*9 + k] * sv[u];
        }
    }
    float acc = bta[0] + s * (1.0f/25.0f);
    g_gt[n*256 + t] = 1.0f + sigm(acc);
}

// ---------------- K7: channel gate ----------------
__global__ __launch_bounds__(64) void k7_cgate(
    const float* __restrict__ W1, const float* __restrict__ b1,
    const float* __restrict__ W2, const float* __restrict__ b2)
{
    __shared__ float gt[256];
    __shared__ float se[64];
    __shared__ float h[32];
    const int tid = threadIdx.x, n = blockIdx.x;
    for (int i = tid; i < 256; i += 64) gt[i] = g_gt[n*256 + i];
    __syncthreads();
    {
        const float* sv = &g_SVw[(n*64 + tid)*256];
        float s = 0.f;
        for (int t = 0; t < 256; ++t) s += sv[t] * gt[t];
        se[tid] = s * (1.0f/6400.0f);
    }
    __syncthreads();
    if (tid < 32) {
        float a = b1[tid];
        for (int c = 0; c < 64; ++c) a += W1[tid*64 + c] * se[c];
        h[tid] = fmaxf(a, 0.f);
    }
    __syncthreads();
    {
        float a = b2[tid];
        #pragma unroll
        for (int j = 0; j < 32; ++j) a += W2[tid*32 + j] * h[j];
        g_gc[n*64 + tid] = 1.0f + sigm(a);
    }
}

// ---------------- K8: finalize ----------------
__global__ __launch_bounds__(256) void k8_final(float* __restrict__ out) {
    const int i4 = blockIdx.x*256 + threadIdx.x;
    if (i4 >= NB*CC*TT*VV/4) return;
    float4 y = ((const float4*)g_y0)[i4];
    float r[4] = {y.x, y.y, y.z, y.w};
    #pragma unroll
    for (int k = 0; k < 4; ++k) {
        unsigned idx = (unsigned)i4*4u + k;
        unsigned row = idx / 25u;
        unsigned v   = idx - row*25u;
        unsigned t   = row & 255u;
        unsigned nc  = row >> 8;
        unsigned n   = nc >> 6;
        r[k] *= g_gs[n*25 + v] * g_gt[n*256 + t] * g_gc[nc];
    }
    ((float4*)out)[i4] = make_float4(r[0], r[1], r[2], r[3]);
}

// ---------------- launch ----------------
extern "C" void kernel_launch(void* const* d_in, const int* in_sizes, int n_in,
                              void* d_out, int out_size) {
    const float* x     = (const float*)d_in[0];
    const float* PA    = (const float*)d_in[1];
    const float* alpha = (const float*)d_in[2];
    const float* Wa    = (const float*)d_in[3];
    const float* ba    = (const float*)d_in[4];
    const float* Wb    = (const float*)d_in[5];
    const float* bb    = (const float*)d_in[6];
    const float* Wd    = (const float*)d_in[7];
    const float* bd    = (const float*)d_in[8];
    const float* gam   = (const float*)d_in[9];
    const float* bet   = (const float*)d_in[10];
    const float* Wsa   = (const float*)d_in[11];
    const float* bsa   = (const float*)d_in[12];
    const float* Wta   = (const float*)d_in[13];
    const float* bta   = (const float*)d_in[14];
    const float* W1    = (const float*)d_in[15];
    const float* b1    = (const float*)d_in[16];
    const float* W2    = (const float*)d_in[17];
    const float* b2    = (const float*)d_in[18];
    float* out = (float*)d_out;

    cudaFuncSetAttribute(k1_emb_adj, cudaFuncAttributeMaxDynamicSharedMemorySize, 68608);
    cudaFuncSetAttribute(k3_main,    cudaFuncAttributeMaxDynamicSharedMemorySize, 49152);

    k0_zero<<<224, 1024>>>();
    k1_emb_adj<<<dim3(8, 64), 256, 67968>>>(x, Wa, ba, Wb, bb);
    k2_adj<<<120, 1024>>>(PA, alpha);
    k3_main<<<dim3(64, 64), 256, 48896>>>(x, Wd, bd, gam, bet);
    k4_sgate<<<64, 128>>>(Wsa, bsa);
    k5_svw<<<dim3(64, 64), 256>>>();
    k6_tgate<<<64, 256>>>(Wta, bta);
    k7_cgate<<<64, 64>>>(W1, b1, W2, b2);
    k8_final<<<25600, 256>>>(out);
}

// round 10
// speedup vs baseline: 1.2204x; 1.2204x over previous
#include <cuda_runtime.h>
#include <math.h>

#define NB 64
#define CC 64
#define TT 256
#define VV 25
#define SS 3
#define II 16

typedef unsigned long long ull;

// ---------------- device scratch ----------------
__device__ float g_A1 [NB*SS*VV*VV];
__device__ float g_Ai [NB*SS*VV*VV];
__device__ float g_y0 [NB*CC*TT*VV];   // ~105MB
__device__ float g_ST [NB*CC*VV];
__device__ float g_SVw[NB*CC*TT];
__device__ float g_gs [NB*VV];
__device__ float g_gt [NB*TT];
__device__ float g_gc [NB*CC];

__device__ __forceinline__ float sigm(float x) { return 1.0f / (1.0f + expf(-x)); }

// packed fp32x2 helpers
__device__ __forceinline__ ull pack2(float f) {
    ull r;
    asm("mov.b64 %0, {%1, %1};" : "=l"(r) : "r"(__float_as_uint(f)));
    return r;
}
__device__ __forceinline__ void fma2(ull& d, ull a, ull b) {
    asm("fma.rn.f32x2 %0, %1, %2, %0;" : "+l"(d) : "l"(a), "l"(b));
}
__device__ __forceinline__ float2 unpack2(ull p) {
    unsigned lo, hi;
    asm("mov.b64 {%0, %1}, %2;" : "=r"(lo), "=r"(hi) : "l"(p));
    return make_float2(__uint_as_float(lo), __uint_as_float(hi));
}

// ---------------- K0 ----------------
__global__ void k0_zero() {
    const int tot = NB*SS*VV*VV + NB*CC*VV;
    for (int i = blockIdx.x*blockDim.x + threadIdx.x; i < tot; i += gridDim.x*blockDim.x) {
        if (i < NB*SS*VV*VV) g_A1[i] = 0.f;
        else                 g_ST[i - NB*SS*VV*VV] = 0.f;
    }
}

// ---------------- K1: embeddings + partial A1 ----------------
// grid (8, 64), 256 threads, dyn smem 67968 B
__global__ __launch_bounds__(256) void k1_emb_adj(
    const float* __restrict__ x,  const float* __restrict__ Wa, const float* __restrict__ ba,
    const float* __restrict__ Wb, const float* __restrict__ bb)
{
    extern __shared__ float sm1[];
    float* Xs  = sm1;             // 6400
    float* Es  = sm1 + 6400;      // 3584: 32 x 112, flat [0,100) per row
    float* Wt3 = sm1 + 9984;      // 6912: [s][c][36-pad j]
    float* bs3 = sm1 + 16896;     // 96

    const int tid = threadIdx.x;
    const int n   = blockIdx.y;

    for (int i = tid; i < 6144; i += 256) {
        int s = i >> 11, r = i & 2047, j = r >> 6, c = r & 63;
        float w = (j < 16) ? Wa[(s*16 + j)*64 + c] : Wb[(s*16 + (j-16))*64 + c];
        Wt3[(s*64 + c)*36 + j] = w;
    }
    if (tid < 96) {
        int s = tid / 32, j = tid % 32;
        bs3[tid] = (j < 16) ? ba[s*16 + j] : bb[s*16 + (j-16)];
    }

    float accA0[SS], accA1[SS], accA2[SS], accA3[SS];
    #pragma unroll
    for (int s = 0; s < SS; ++s) { accA0[s]=0.f; accA1[s]=0.f; accA2[s]=0.f; accA3[s]=0.f; }
    const bool hasA = tid < 175;
    const int  vA = tid / 7, w4A = tid % 7;
    const bool hasE = tid < 200;
    const int  jg = tid / 25, q = tid % 25;

    __syncthreads();

    for (int sub = 0; sub < 8; ++sub) {
        const int tile = blockIdx.x * 8 + sub;
        __syncthreads();
        {
            const float4* xg = (const float4*)x;
            float4* Xs4 = (float4*)Xs;
            for (int i = tid; i < 1600; i += 256) {
                int c = i / 25, qq = i - c*25;
                Xs4[c*25 + qq] = xg[(n*64 + c)*1600 + tile*25 + qq];
            }
        }
        __syncthreads();

        for (int s = 0; s < SS; ++s) {
            if (hasE) {
                const ulonglong2* Xs2 = (const ulonglong2*)Xs;
                const float* wb_ = Wt3 + s*64*36;
                const float* bsp = bs3 + s*32 + jg*4;
                ull a0x = pack2(bsp[0]), a0y = a0x;
                ull a1x = pack2(bsp[1]), a1y = a1x;
                ull a2x = pack2(bsp[2]), a2y = a2x;
                ull a3x = pack2(bsp[3]), a3y = a3x;
                #pragma unroll 8
                for (int c = 0; c < 64; ++c) {
                    float4 wv = *(const float4*)(wb_ + c*36 + jg*4);
                    ulonglong2 xv = Xs2[c*25 + q];
                    ull w0 = pack2(wv.x), w1 = pack2(wv.y), w2 = pack2(wv.z), w3 = pack2(wv.w);
                    fma2(a0x, w0, xv.x); fma2(a0y, w0, xv.y);
                    fma2(a1x, w1, xv.x); fma2(a1y, w1, xv.y);
                    fma2(a2x, w2, xv.x); fma2(a2y, w2, xv.y);
                    fma2(a3x, w3, xv.x); fma2(a3y, w3, xv.y);
                }
                ulonglong2* Es2 = (ulonglong2*)Es;
                Es2[(jg*4+0)*28 + q] = make_ulonglong2(a0x, a0y);
                Es2[(jg*4+1)*28 + q] = make_ulonglong2(a1x, a1y);
                Es2[(jg*4+2)*28 + q] = make_ulonglong2(a2x, a2y);
                Es2[(jg*4+3)*28 + q] = make_ulonglong2(a3x, a3y);
            }
            __syncthreads();

            if (hasA) {
                float c0 = accA0[s], c1 = accA1[s], c2 = accA2[s], c3 = accA3[s];
                #pragma unroll 4
                for (int j = 0; j < 16; ++j) {
                    #pragma unroll
                    for (int t = 0; t < 4; ++t) {
                        float av = Es[j*112 + t*25 + vA];
                        const float* br = &Es[(16+j)*112 + t*25 + w4A*4];
                        c0 += av*br[0]; c1 += av*br[1]; c2 += av*br[2]; c3 += av*br[3];
                    }
                }
                accA0[s] = c0; accA1[s] = c1; accA2[s] = c2; accA3[s] = c3;
            }
            __syncthreads();
        }
    }

    if (hasA) {
        #pragma unroll
        for (int s = 0; s < SS; ++s) {
            float* dst = &g_A1[((n*SS + s)*VV + vA)*VV];
            float vals[4] = {accA0[s], accA1[s], accA2[s], accA3[s]};
            #pragma unroll
            for (int k = 0; k < 4; ++k) {
                int w = w4A*4 + k;
                if (w < VV) atomicAdd(&dst[w], vals[k]);
            }
        }
    }
}

// ---------------- K2 ----------------
__global__ void k2_adj(const float* __restrict__ PA, const float* __restrict__ alpha) {
    const float al = alpha[0];
    const int tot = NB*SS*VV*VV;
    for (int i = blockIdx.x*blockDim.x + threadIdx.x; i < tot; i += gridDim.x*blockDim.x)
        g_Ai[i] = PA[i % (SS*VV*VV)] + al * tanhf(g_A1[i] * (1.0f/4096.0f));
}

// ---------------- K3: fused (Wd@X)@Ai — no Z round-trip ----------------
// grid (64, 64), 256 threads, dyn smem 48896 B
// thread = (o = tid>>2, t = tid&3); Y[o][t][0..27] accumulated across s.
__global__ __launch_bounds__(256, 3) void k3_main(
    const float* __restrict__ x,  const float* __restrict__ Wd, const float* __restrict__ bd,
    const float* __restrict__ gamma, const float* __restrict__ beta)
{
    extern __shared__ float sm[];
    float* Xs  = sm;            // 7168: [c][t*28+v]  (stride 112, v pad 25..27 = 0)
    float* Ais = sm + 7168;     // 704:  [25][28] pad cols zeroed
    float* Wds = sm + 7872;     // 4352: [o][68-pad c]

    const int tid  = threadIdx.x;
    const int n    = blockIdx.y;
    const int tile = blockIdx.x;        // t0 = tile*4
    const int o    = tid >> 2;
    const int t    = tid & 3;

    // zero Ai pad cols + Xs pad cols
    if (tid < 25) { Ais[tid*28+25] = 0.f; Ais[tid*28+26] = 0.f; Ais[tid*28+27] = 0.f; }
    for (int i = tid; i < 768; i += 256) {
        int c = i / 12, r = i - c*12, tt = r / 3, k = r - tt*3;
        Xs[c*112 + tt*28 + 25 + k] = 0.f;
    }
    // load X tile into padded layout (float4 load, scalar scatter)
    {
        const float4* xg = (const float4*)x;
        for (int i = tid; i < 1600; i += 256) {
            int c = i / 25, qq = i - c*25;
            float4 v4 = xg[(n*64 + c)*1600 + tile*25 + qq];
            int j = qq*4;
            float vals[4] = {v4.x, v4.y, v4.z, v4.w};
            #pragma unroll
            for (int k = 0; k < 4; ++k) {
                int tt = (j+k) / 25, v = (j+k) - tt*25;
                Xs[c*112 + tt*28 + v] = vals[k];
            }
        }
    }

    ull Y[14];
    #pragma unroll
    for (int k = 0; k < 14; ++k) Y[k] = 0ULL;

    for (int s = 0; s < SS; ++s) {
        __syncthreads();   // protect Ais/Wds from previous readers (also covers Xs init at s=0)
        for (int i = tid; i < 625; i += 256) Ais[(i/25)*28 + (i%25)] = g_Ai[(n*SS + s)*625 + i];
        {
            const float4* wg = (const float4*)(Wd + s*4096);
            for (int i4 = tid; i4 < 1024; i4 += 256) {
                int oo = i4 >> 4, c4 = i4 & 15;
                *(float4*)(Wds + oo*68 + c4*4) = wg[i4];
            }
        }
        __syncthreads();

        // stage 1: U[v] = sum_c Wd[o][c] * X[c][t][v]   (v packed in 14 ull, pads are 0)
        ull U[14];
        #pragma unroll
        for (int k = 0; k < 14; ++k) U[k] = 0ULL;
        {
            const float* wr = Wds + o*68;
            const float* xb = Xs + t*28;
            #pragma unroll 2
            for (int c = 0; c < 64; c += 4) {
                float4 wv = *(const float4*)(wr + c);
                float wvs[4] = {wv.x, wv.y, wv.z, wv.w};
                #pragma unroll
                for (int j = 0; j < 4; ++j) {
                    ull wp = pack2(wvs[j]);
                    const ulonglong2* xp = (const ulonglong2*)(xb + (c+j)*112);
                    #pragma unroll
                    for (int w4 = 0; w4 < 7; ++w4) {
                        ulonglong2 xv = xp[w4];
                        fma2(U[2*w4], wp, xv.x); fma2(U[2*w4+1], wp, xv.y);
                    }
                }
            }
        }

        // stage 2: Y[w] += sum_v U[v] * Ai[v][w]   (Ai rows = pure broadcast loads)
        #pragma unroll
        for (int v = 0; v < 25; ++v) {
            float2 fu = unpack2(U[v >> 1]);
            ull uv = pack2((v & 1) ? fu.y : fu.x);
            const ulonglong2* ap = (const ulonglong2*)(Ais + v*28);
            #pragma unroll
            for (int w4 = 0; w4 < 7; ++w4) {
                ulonglong2 av = ap[w4];
                fma2(Y[2*w4], uv, av.x); fma2(Y[2*w4+1], uv, av.y);
            }
        }
    }

    // epilogue: bias + BN + residual (from Xs) + relu
    float yv[28];
    #pragma unroll
    for (int k = 0; k < 14; ++k) {
        float2 f = unpack2(Y[k]); yv[2*k] = f.x; yv[2*k+1] = f.y;
    }
    {
        const float scl  = rsqrtf(1.0f + 1e-5f);
        const float bsum = bd[o] + bd[64+o] + bd[128+o];
        const float scv  = gamma[o]*scl;
        const float btv  = beta[o];
        const float* xr = Xs + o*112 + t*28;
        #pragma unroll
        for (int w = 0; w < 25; ++w)
            yv[w] = fmaxf((yv[w] + bsum)*scv + btv + xr[w], 0.f);
    }
    __syncthreads();   // all residual reads of Xs done
    // stage y0 into Xs flat [o][t*25+w] (stride 100)
    #pragma unroll
    for (int w = 0; w < 25; ++w) Xs[o*100 + t*25 + w] = yv[w];
    __syncthreads();

    {   // coalesced y0 store + ST atomic accumulate
        float4* yg = (float4*)g_y0;
        const float4* Xs4 = (const float4*)Xs;
        for (int i = tid; i < 1600; i += 256) {
            int c = i / 25, qq = i - c*25;
            yg[(n*64 + c)*1600 + tile*25 + qq] = Xs4[c*25 + qq];
        }
        for (int i = tid; i < 1600; i += 256) {
            int c = i / 25, v = i - c*25;
            float ssum = Xs[c*100 + v] + Xs[c*100 + 25 + v]
                       + Xs[c*100 + 50 + v] + Xs[c*100 + 75 + v];
            atomicAdd(&g_ST[n*1600 + i], ssum);
        }
    }
}

// ---------------- K4: spatial gate ----------------
__global__ __launch_bounds__(128) void k4_sgate(const float* __restrict__ Wsa,
                                                const float* __restrict__ bsa)
{
    __shared__ float se[1600];
    __shared__ float wk[1600];
    const int tid = threadIdx.x, n = blockIdx.x;
    for (int i = tid; i < 1600; i += 128) {
        se[i] = g_ST[n*1600 + i] * (1.0f/256.0f);
        wk[i] = Wsa[i];
    }
    __syncthreads();
    if (tid < VV) {
        int v = tid;
        float acc = bsa[0];
        for (int c = 0; c < 64; ++c)
            #pragma unroll
            for (int k = 0; k < 25; ++k) {
                int u = v + k - 12;
                if (u >= 0 && u < 25) acc += wk[c*25 + k] * se[c*25 + u];
            }
        g_gs[n*25 + v] = 1.0f + sigm(acc);
    }
}

// ---------------- K5: SVw = sum_v y0*(1+gs) ----------------
__global__ __launch_bounds__(256) void k5_svw() {
    __shared__ float gs[25];
    const int c = blockIdx.x, n = blockIdx.y, t = threadIdx.x;
    if (t < 25) gs[t] = g_gs[n*25 + t];
    __syncthreads();
    const float* row = &g_y0[((n*64 + c)*256 + t)*25];
    float s = 0.f;
    #pragma unroll
    for (int v = 0; v < 25; ++v) s += row[v] * gs[v];
    g_SVw[(n*64 + c)*256 + t] = s;
}

// ---------------- K6: temporal gate ----------------
__global__ __launch_bounds__(256) void k6_tgate(const float* __restrict__ Wta,
                                                const float* __restrict__ bta)
{
    __shared__ float wk[576];
    const int tid = threadIdx.x, n = blockIdx.x;
    for (int i = tid; i < 576; i += 256) wk[i] = Wta[i];
    __syncthreads();
    const int t = tid;
    float s = 0.f;
    for (int c = 0; c < 64; ++c) {
        const float* sv = &g_SVw[(n*64 + c)*256];
        #pragma unroll
        for (int k = 0; k < 9; ++k) {
            int u = t + k - 4;
            if (u >= 0 && u < 256) s += wk[c*9 + k] * sv[u];
        }
    }
    float acc = bta[0] + s * (1.0f/25.0f);
    g_gt[n*256 + t] = 1.0f + sigm(acc);
}

// ---------------- K7: channel gate ----------------
__global__ __launch_bounds__(64) void k7_cgate(
    const float* __restrict__ W1, const float* __restrict__ b1,
    const float* __restrict__ W2, const float* __restrict__ b2)
{
    __shared__ float gt[256];
    __shared__ float se[64];
    __shared__ float h[32];
    const int tid = threadIdx.x, n = blockIdx.x;
    for (int i = tid; i < 256; i += 64) gt[i] = g_gt[n*256 + i];
    __syncthreads();
    {
        const float* sv = &g_SVw[(n*64 + tid)*256];
        float s = 0.f;
        for (int t = 0; t < 256; ++t) s += sv[t] * gt[t];
        se[tid] = s * (1.0f/6400.0f);
    }
    __syncthreads();
    if (tid < 32) {
        float a = b1[tid];
        for (int c = 0; c < 64; ++c) a += W1[tid*64 + c] * se[c];
        h[tid] = fmaxf(a, 0.f);
    }
    __syncthreads();
    {
        float a = b2[tid];
        #pragma unroll
        for (int j = 0; j < 32; ++j) a += W2[tid*32 + j] * h[j];
        g_gc[n*64 + tid] = 1.0f + sigm(a);
    }
}

// ---------------- K8: finalize ----------------
__global__ __launch_bounds__(256) void k8_final(float* __restrict__ out) {
    const int i4 = blockIdx.x*256 + threadIdx.x;
    if (i4 >= NB*CC*TT*VV/4) return;
    float4 y = ((const float4*)g_y0)[i4];
    float r[4] = {y.x, y.y, y.z, y.w};
    #pragma unroll
    for (int k = 0; k < 4; ++k) {
        unsigned idx = (unsigned)i4*4u + k;
        unsigned row = idx / 25u;
        unsigned v   = idx - row*25u;
        unsigned t   = row & 255u;
        unsigned nc  = row >> 8;
        unsigned n   = nc >> 6;
        r[k] *= g_gs[n*25 + v] * g_gt[n*256 + t] * g_gc[nc];
    }
    ((float4*)out)[i4] = make_float4(r[0], r[1], r[2], r[3]);
}

// ---------------- launch ----------------
extern "C" void kernel_launch(void* const* d_in, const int* in_sizes, int n_in,
                              void* d_out, int out_size) {
    const float* x     = (const float*)d_in[0];
    const float* PA    = (const float*)d_in[1];
    const float* alpha = (const float*)d_in[2];
    const float* Wa    = (const float*)d_in[3];
    const float* ba    = (const float*)d_in[4];
    const float* Wb    = (const float*)d_in[5];
    const float* bb    = (const float*)d_in[6];
    const float* Wd    = (const float*)d_in[7];
    const float* bd    = (const float*)d_in[8];
    const float* gam   = (const float*)d_in[9];
    const float* bet   = (const float*)d_in[10];
    const float* Wsa   = (const float*)d_in[11];
    const float* bsa   = (const float*)d_in[12];
    const float* Wta   = (const float*)d_in[13];
    const float* bta   = (const float*)d_in[14];
    const float* W1    = (const float*)d_in[15];
    const float* b1    = (const float*)d_in[16];
    const float* W2    = (const float*)d_in[17];
    const float* b2    = (const float*)d_in[18];
    float* out = (float*)d_out;

    cudaFuncSetAttribute(k1_emb_adj, cudaFuncAttributeMaxDynamicSharedMemorySize, 68608);
    cudaFuncSetAttribute(k3_main,    cudaFuncAttributeMaxDynamicSharedMemorySize, 49152);

    k0_zero<<<224, 1024>>>();
    k1_emb_adj<<<dim3(8, 64), 256, 67968>>>(x, Wa, ba, Wb, bb);
    k2_adj<<<120, 1024>>>(PA, alpha);
    k3_main<<<dim3(64, 64), 256, 48896>>>(x, Wd, bd, gam, bet);
    k4_sgate<<<64, 128>>>(Wsa, bsa);
    k5_svw<<<dim3(64, 64), 256>>>();
    k6_tgate<<<64, 256>>>(Wta, bta);
    k7_cgate<<<64, 64>>>(W1, b1, W2, b2);
    k8_final<<<25600, 256>>>(out);
}

// round 11
// speedup vs baseline: 1.4886x; 1.2198x over previous
#include <cuda_runtime.h>
#include <math.h>

#define NB 64
#define CC 64
#define TT 256
#define VV 25
#define SS 3
#define II 16

typedef unsigned long long ull;

// ---------------- device scratch ----------------
__device__ float g_A1 [NB*SS*VV*VV];
__device__ float g_Ai [NB*SS*VV*VV];
__device__ float g_y0 [NB*CC*TT*VV];   // ~105MB
__device__ float g_ST [NB*CC*VV];
__device__ float g_SVw[NB*CC*TT];
__device__ float g_gs [NB*VV];
__device__ float g_gt [NB*TT];
__device__ float g_gc [NB*CC];

__device__ __forceinline__ float sigm(float x) { return 1.0f / (1.0f + expf(-x)); }

// packed fp32x2 helpers
__device__ __forceinline__ ull pack2(float f) {
    ull r;
    asm("mov.b64 %0, {%1, %1};" : "=l"(r) : "r"(__float_as_uint(f)));
    return r;
}
__device__ __forceinline__ void fma2(ull& d, ull a, ull b) {
    asm("fma.rn.f32x2 %0, %1, %2, %0;" : "+l"(d) : "l"(a), "l"(b));
}
__device__ __forceinline__ float2 unpack2(ull p) {
    unsigned lo, hi;
    asm("mov.b64 {%0, %1}, %2;" : "=r"(lo), "=r"(hi) : "l"(p));
    return make_float2(__uint_as_float(lo), __uint_as_float(hi));
}

// ---------------- K0 ----------------
__global__ void k0_zero() {
    const int tot = NB*SS*VV*VV + NB*CC*VV;
    for (int i = blockIdx.x*blockDim.x + threadIdx.x; i < tot; i += gridDim.x*blockDim.x) {
        if (i < NB*SS*VV*VV) g_A1[i] = 0.f;
        else                 g_ST[i - NB*SS*VV*VV] = 0.f;
    }
}

// ---------------- K1: embeddings + partial A1 ----------------
// grid (8, 64), 256 threads, dyn smem 67968 B
__global__ __launch_bounds__(256) void k1_emb_adj(
    const float* __restrict__ x,  const float* __restrict__ Wa, const float* __restrict__ ba,
    const float* __restrict__ Wb, const float* __restrict__ bb)
{
    extern __shared__ float sm1[];
    float* Xs  = sm1;             // 6400
    float* Es  = sm1 + 6400;      // 3584: 32 x 112, flat [0,100) per row
    float* Wt3 = sm1 + 9984;      // 6912: [s][c][36-pad j]
    float* bs3 = sm1 + 16896;     // 96

    const int tid = threadIdx.x;
    const int n   = blockIdx.y;

    for (int i = tid; i < 6144; i += 256) {
        int s = i >> 11, r = i & 2047, j = r >> 6, c = r & 63;
        float w = (j < 16) ? Wa[(s*16 + j)*64 + c] : Wb[(s*16 + (j-16))*64 + c];
        Wt3[(s*64 + c)*36 + j] = w;
    }
    if (tid < 96) {
        int s = tid / 32, j = tid % 32;
        bs3[tid] = (j < 16) ? ba[s*16 + j] : bb[s*16 + (j-16)];
    }

    float accA0[SS], accA1[SS], accA2[SS], accA3[SS];
    #pragma unroll
    for (int s = 0; s < SS; ++s) { accA0[s]=0.f; accA1[s]=0.f; accA2[s]=0.f; accA3[s]=0.f; }
    const bool hasA = tid < 175;
    const int  vA = tid / 7, w4A = tid % 7;
    const bool hasE = tid < 200;
    const int  jg = tid / 25, q = tid % 25;

    __syncthreads();

    for (int sub = 0; sub < 8; ++sub) {
        const int tile = blockIdx.x * 8 + sub;
        __syncthreads();
        {
            const float4* xg = (const float4*)x;
            float4* Xs4 = (float4*)Xs;
            for (int i = tid; i < 1600; i += 256) {
                int c = i / 25, qq = i - c*25;
                Xs4[c*25 + qq] = xg[(n*64 + c)*1600 + tile*25 + qq];
            }
        }
        __syncthreads();

        for (int s = 0; s < SS; ++s) {
            if (hasE) {
                const ulonglong2* Xs2 = (const ulonglong2*)Xs;
                const float* wb_ = Wt3 + s*64*36;
                const float* bsp = bs3 + s*32 + jg*4;
                ull a0x = pack2(bsp[0]), a0y = a0x;
                ull a1x = pack2(bsp[1]), a1y = a1x;
                ull a2x = pack2(bsp[2]), a2y = a2x;
                ull a3x = pack2(bsp[3]), a3y = a3x;
                #pragma unroll 8
                for (int c = 0; c < 64; ++c) {
                    float4 wv = *(const float4*)(wb_ + c*36 + jg*4);
                    ulonglong2 xv = Xs2[c*25 + q];
                    ull w0 = pack2(wv.x), w1 = pack2(wv.y), w2 = pack2(wv.z), w3 = pack2(wv.w);
                    fma2(a0x, w0, xv.x); fma2(a0y, w0, xv.y);
                    fma2(a1x, w1, xv.x); fma2(a1y, w1, xv.y);
                    fma2(a2x, w2, xv.x); fma2(a2y, w2, xv.y);
                    fma2(a3x, w3, xv.x); fma2(a3y, w3, xv.y);
                }
                ulonglong2* Es2 = (ulonglong2*)Es;
                Es2[(jg*4+0)*28 + q] = make_ulonglong2(a0x, a0y);
                Es2[(jg*4+1)*28 + q] = make_ulonglong2(a1x, a1y);
                Es2[(jg*4+2)*28 + q] = make_ulonglong2(a2x, a2y);
                Es2[(jg*4+3)*28 + q] = make_ulonglong2(a3x, a3y);
            }
            __syncthreads();

            if (hasA) {
                float c0 = accA0[s], c1 = accA1[s], c2 = accA2[s], c3 = accA3[s];
                #pragma unroll 4
                for (int j = 0; j < 16; ++j) {
                    #pragma unroll
                    for (int t = 0; t < 4; ++t) {
                        float av = Es[j*112 + t*25 + vA];
                        const float* br = &Es[(16+j)*112 + t*25 + w4A*4];
                        c0 += av*br[0]; c1 += av*br[1]; c2 += av*br[2]; c3 += av*br[3];
                    }
                }
                accA0[s] = c0; accA1[s] = c1; accA2[s] = c2; accA3[s] = c3;
            }
            __syncthreads();
        }
    }

    if (hasA) {
        #pragma unroll
        for (int s = 0; s < SS; ++s) {
            float* dst = &g_A1[((n*SS + s)*VV + vA)*VV];
            float vals[4] = {accA0[s], accA1[s], accA2[s], accA3[s]};
            #pragma unroll
            for (int k = 0; k < 4; ++k) {
                int w = w4A*4 + k;
                if (w < VV) atomicAdd(&dst[w], vals[k]);
            }
        }
    }
}

// ---------------- K2 ----------------
__global__ void k2_adj(const float* __restrict__ PA, const float* __restrict__ alpha) {
    const float al = alpha[0];
    const int tot = NB*SS*VV*VV;
    for (int i = blockIdx.x*blockDim.x + threadIdx.x; i < tot; i += gridDim.x*blockDim.x)
        g_Ai[i] = PA[i % (SS*VV*VV)] + al * tanhf(g_A1[i] * (1.0f/4096.0f));
}

// ---------------- K3: fused (Wd@X)@Ai — o-major lanes, broadcast LDS ----------------
// grid (64, 64), 256 threads, dyn smem 48128 B, 2 blocks/SM (128 regs)
// thread = (o = tid&63, t = tid>>6): each warp has ONE t, 32 consecutive o's.
__global__ __launch_bounds__(256, 2) void k3_main(
    const float* __restrict__ x,  const float* __restrict__ Wd, const float* __restrict__ bd,
    const float* __restrict__ gamma, const float* __restrict__ beta)
{
    extern __shared__ float sm[];
    float* Xs  = sm;            // 7168: [c][t*28+v]  (stride 112, pads v=25..27 zero)
    float* Ais = sm + 7168;     // 704:  [25][28] pad cols zeroed
    float* Wds = sm + 7872;     // 4160: [c][65-pad o]

    const int tid  = threadIdx.x;
    const int n    = blockIdx.y;
    const int tile = blockIdx.x;        // t0 = tile*4
    const int o    = tid & 63;
    const int t    = tid >> 6;

    // zero Ai pad cols + Xs pad cols
    if (tid < 25) { Ais[tid*28+25] = 0.f; Ais[tid*28+26] = 0.f; Ais[tid*28+27] = 0.f; }
    for (int i = tid; i < 768; i += 256) {
        int c = i / 12, r = i - c*12, tt = r / 3, k = r - tt*3;
        Xs[c*112 + tt*28 + 25 + k] = 0.f;
    }
    // load X tile into padded layout (float4 load, scalar scatter)
    {
        const float4* xg = (const float4*)x;
        for (int i = tid; i < 1600; i += 256) {
            int c = i / 25, qq = i - c*25;
            float4 v4 = xg[(n*64 + c)*1600 + tile*25 + qq];
            int j = qq*4;
            float vals[4] = {v4.x, v4.y, v4.z, v4.w};
            #pragma unroll
            for (int k = 0; k < 4; ++k) {
                int tt = (j+k) / 25, v = (j+k) - tt*25;
                Xs[c*112 + tt*28 + v] = vals[k];
            }
        }
    }

    ull Y[14];
    #pragma unroll
    for (int k = 0; k < 14; ++k) Y[k] = 0ULL;

    for (int s = 0; s < SS; ++s) {
        __syncthreads();   // protect Ais/Wds from previous readers (covers Xs init at s=0)
        for (int i = tid; i < 625; i += 256) Ais[(i/25)*28 + (i%25)] = g_Ai[(n*SS + s)*625 + i];
        // Wd[s][o][c] -> Wds[c][o] (pad 65): linear global read, conflict-free smem write
        for (int i = tid; i < 4096; i += 256) {
            int oo = i >> 6, c = i & 63;
            Wds[c*65 + oo] = Wd[s*4096 + i];
        }
        __syncthreads();

        // stage 1: U[v] = sum_c Wd[o][c] * X[c][t][v]
        // X loads: whole warp reads the same address (one t per warp) -> broadcast.
        // W loads: lane-consecutive o -> conflict-free.
        ull U[14];
        #pragma unroll
        for (int k = 0; k < 14; ++k) U[k] = 0ULL;
        {
            const float* xb = Xs + t*28;
            #pragma unroll 4
            for (int c = 0; c < 64; ++c) {
                ull wp = pack2(Wds[c*65 + o]);
                const ulonglong2* xp = (const ulonglong2*)(xb + c*112);
                #pragma unroll
                for (int w4 = 0; w4 < 7; ++w4) {
                    ulonglong2 xv = xp[w4];
                    fma2(U[2*w4], wp, xv.x); fma2(U[2*w4+1], wp, xv.y);
                }
            }
        }

        // stage 2: Y[w] += sum_v U[v] * Ai[v][w]  (Ai rows = pure broadcast)
        #pragma unroll
        for (int v = 0; v < 25; ++v) {
            float2 fu = unpack2(U[v >> 1]);
            ull uv = pack2((v & 1) ? fu.y : fu.x);
            const ulonglong2* ap = (const ulonglong2*)(Ais + v*28);
            #pragma unroll
            for (int w4 = 0; w4 < 7; ++w4) {
                ulonglong2 av = ap[w4];
                fma2(Y[2*w4], uv, av.x); fma2(Y[2*w4+1], uv, av.y);
            }
        }
    }

    // epilogue: bias + BN + residual (from Xs) + relu
    float yv[28];
    #pragma unroll
    for (int k = 0; k < 14; ++k) {
        float2 f = unpack2(Y[k]); yv[2*k] = f.x; yv[2*k+1] = f.y;
    }
    {
        const float scl  = rsqrtf(1.0f + 1e-5f);
        const float bsum = bd[o] + bd[64+o] + bd[128+o];
        const float scv  = gamma[o]*scl;
        const float btv  = beta[o];
        const float* xr = Xs + o*112 + t*28;
        #pragma unroll
        for (int w = 0; w < 25; ++w)
            yv[w] = fmaxf((yv[w] + bsum)*scv + btv + xr[w], 0.f);
    }
    __syncthreads();   // all residual reads of Xs done
    // stage y0 into Xs flat [o][t*25+w] (stride 100)
    #pragma unroll
    for (int w = 0; w < 25; ++w) Xs[o*100 + t*25 + w] = yv[w];
    __syncthreads();

    {   // coalesced y0 store + ST atomic accumulate
        float4* yg = (float4*)g_y0;
        const float4* Xs4 = (const float4*)Xs;
        for (int i = tid; i < 1600; i += 256) {
            int c = i / 25, qq = i - c*25;
            yg[(n*64 + c)*1600 + tile*25 + qq] = Xs4[c*25 + qq];
        }
        for (int i = tid; i < 1600; i += 256) {
            int c = i / 25, v = i - c*25;
            float ssum = Xs[c*100 + v] + Xs[c*100 + 25 + v]
                       + Xs[c*100 + 50 + v] + Xs[c*100 + 75 + v];
            atomicAdd(&g_ST[n*1600 + i], ssum);
        }
    }
}

// ---------------- K4: spatial gate ----------------
__global__ __launch_bounds__(128) void k4_sgate(const float* __restrict__ Wsa,
                                                const float* __restrict__ bsa)
{
    __shared__ float se[1600];
    __shared__ float wk[1600];
    const int tid = threadIdx.x, n = blockIdx.x;
    for (int i = tid; i < 1600; i += 128) {
        se[i] = g_ST[n*1600 + i] * (1.0f/256.0f);
        wk[i] = Wsa[i];
    }
    __syncthreads();
    if (tid < VV) {
        int v = tid;
        float acc = bsa[0];
        for (int c = 0; c < 64; ++c)
            #pragma unroll
            for (int k = 0; k < 25; ++k) {
                int u = v + k - 12;
                if (u >= 0 && u < 25) acc += wk[c*25 + k] * se[c*25 + u];
            }
        g_gs[n*25 + v] = 1.0f + sigm(acc);
    }
}

// ---------------- K5: SVw = sum_v y0*(1+gs) ----------------
__global__ __launch_bounds__(256) void k5_svw() {
    __shared__ float gs[25];
    const int c = blockIdx.x, n = blockIdx.y, t = threadIdx.x;
    if (t < 25) gs[t] = g_gs[n*25 + t];
    __syncthreads();
    const float* row = &g_y0[((n*64 + c)*256 + t)*25];
    float s = 0.f;
    #pragma unroll
    for (int v = 0; v < 25; ++v) s += row[v] * gs[v];
    g_SVw[(n*64 + c)*256 + t] = s;
}

// ---------------- K6: temporal gate ----------------
__global__ __launch_bounds__(256) void k6_tgate(const float* __restrict__ Wta,
                                                const float* __restrict__ bta)
{
    __shared__ float wk[576];
    const int tid = threadIdx.x, n = blockIdx.x;
    for (int i = tid; i < 576; i += 256) wk[i] = Wta[i];
    __syncthreads();
    const int t = tid;
    float s = 0.f;
    for (int c = 0; c < 64; ++c) {
        const float* sv = &g_SVw[(n*64 + c)*256];
        #pragma unroll
        for (int k = 0; k < 9; ++k) {
            int u = t + k - 4;
            if (u >= 0 && u < 256) s += wk[c*9 + k] * sv[u];
        }
    }
    float acc = bta[0] + s * (1.0f/25.0f);
    g_gt[n*256 + t] = 1.0f + sigm(acc);
}

// ---------------- K7: channel gate ----------------
__global__ __launch_bounds__(64) void k7_cgate(
    const float* __restrict__ W1, const float* __restrict__ b1,
    const float* __restrict__ W2, const float* __restrict__ b2)
{
    __shared__ float gt[256];
    __shared__ float se[64];
    __shared__ float h[32];
    const int tid = threadIdx.x, n = blockIdx.x;
    for (int i = tid; i < 256; i += 64) gt[i] = g_gt[n*256 + i];
    __syncthreads();
    {
        const float* sv = &g_SVw[(n*64 + tid)*256];
        float s = 0.f;
        for (int t = 0; t < 256; ++t) s += sv[t] * gt[t];
        se[tid] = s * (1.0f/6400.0f);
    }
    __syncthreads();
    if (tid < 32) {
        float a = b1[tid];
        for (int c = 0; c < 64; ++c) a += W1[tid*64 + c] * se[c];
        h[tid] = fmaxf(a, 0.f);
    }
    __syncthreads();
    {
        float a = b2[tid];
        #pragma unroll
        for (int j = 0; j < 32; ++j) a += W2[tid*32 + j] * h[j];
        g_gc[n*64 + tid] = 1.0f + sigm(a);
    }
}

// ---------------- K8: finalize ----------------
__global__ __launch_bounds__(256) void k8_final(float* __restrict__ out) {
    const int i4 = blockIdx.x*256 + threadIdx.x;
    if (i4 >= NB*CC*TT*VV/4) return;
    float4 y = ((const float4*)g_y0)[i4];
    float r[4] = {y.x, y.y, y.z, y.w};
    #pragma unroll
    for (int k = 0; k < 4; ++k) {
        unsigned idx = (unsigned)i4*4u + k;
        unsigned row = idx / 25u;
        unsigned v   = idx - row*25u;
        unsigned t   = row & 255u;
        unsigned nc  = row >> 8;
        unsigned n   = nc >> 6;
        r[k] *= g_gs[n*25 + v] * g_gt[n*256 + t] * g_gc[nc];
    }
    ((float4*)out)[i4] = make_float4(r[0], r[1], r[2], r[3]);
}

// ---------------- launch ----------------
extern "C" void kernel_launch(void* const* d_in, const int* in_sizes, int n_in,
                              void* d_out, int out_size) {
    const float* x     = (const float*)d_in[0];
    const float* PA    = (const float*)d_in[1];
    const float* alpha = (const float*)d_in[2];
    const float* Wa    = (const float*)d_in[3];
    const float* ba    = (const float*)d_in[4];
    const float* Wb    = (const float*)d_in[5];
    const float* bb    = (const float*)d_in[6];
    const float* Wd    = (const float*)d_in[7];
    const float* bd    = (const float*)d_in[8];
    const float* gam   = (const float*)d_in[9];
    const float* bet   = (const float*)d_in[10];
    const float* Wsa   = (const float*)d_in[11];
    const float* bsa   = (const float*)d_in[12];
    const float* Wta   = (const float*)d_in[13];
    const float* bta   = (const float*)d_in[14];
    const float* W1    = (const float*)d_in[15];
    const float* b1    = (const float*)d_in[16];
    const float* W2    = (const float*)d_in[17];
    const float* b2    = (const float*)d_in[18];
    float* out = (float*)d_out;

    cudaFuncSetAttribute(k1_emb_adj, cudaFuncAttributeMaxDynamicSharedMemorySize, 68608);
    cudaFuncSetAttribute(k3_main,    cudaFuncAttributeMaxDynamicSharedMemorySize, 49152);

    k0_zero<<<224, 1024>>>();
    k1_emb_adj<<<dim3(8, 64), 256, 67968>>>(x, Wa, ba, Wb, bb);
    k2_adj<<<120, 1024>>>(PA, alpha);
    k3_main<<<dim3(64, 64), 256, 48128>>>(x, Wd, bd, gam, bet);
    k4_sgate<<<64, 128>>>(Wsa, bsa);
    k5_svw<<<dim3(64, 64), 256>>>();
    k6_tgate<<<64, 256>>>(Wta, bta);
    k7_cgate<<<64, 64>>>(W1, b1, W2, b2);
    k8_final<<<25600, 256>>>(out);
}

// round 12
// speedup vs baseline: 1.5420x; 1.0358x over previous
#include <cuda_runtime.h>
#include <math.h>

#define NB 64
#define CC 64
#define TT 256
#define VV 25
#define SS 3
#define II 16

typedef unsigned long long ull;

// ---------------- device scratch ----------------
__device__ float g_A1 [NB*SS*VV*VV];
__device__ float g_Ai [NB*SS*VV*VV];
__device__ float g_y0 [NB*CC*TT*VV];   // ~105MB
__device__ float g_ST [NB*CC*VV];
__device__ float g_SVw[NB*CC*TT];
__device__ float g_gs [NB*VV];
__device__ float g_gt [NB*TT];
__device__ float g_gc [NB*CC];

__device__ __forceinline__ float sigm(float x) { return 1.0f / (1.0f + expf(-x)); }

// packed fp32x2 helpers
__device__ __forceinline__ ull pack2(float f) {
    ull r;
    asm("mov.b64 %0, {%1, %1};" : "=l"(r) : "r"(__float_as_uint(f)));
    return r;
}
__device__ __forceinline__ void fma2(ull& d, ull a, ull b) {
    asm("fma.rn.f32x2 %0, %1, %2, %0;" : "+l"(d) : "l"(a), "l"(b));
}
__device__ __forceinline__ float2 unpack2(ull p) {
    unsigned lo, hi;
    asm("mov.b64 {%0, %1}, %2;" : "=r"(lo), "=r"(hi) : "l"(p));
    return make_float2(__uint_as_float(lo), __uint_as_float(hi));
}

// ---------------- K0 ----------------
__global__ void k0_zero() {
    const int tot = NB*SS*VV*VV + NB*CC*VV;
    for (int i = blockIdx.x*blockDim.x + threadIdx.x; i < tot; i += gridDim.x*blockDim.x) {
        if (i < NB*SS*VV*VV) g_A1[i] = 0.f;
        else                 g_ST[i - NB*SS*VV*VV] = 0.f;
    }
}

// ---------------- K1: embeddings + partial A1 (padded layouts) ----------------
// grid (8, 64), 256 threads, dyn smem 71040 B
// Xs: [c][112] padded (t*28+v, pads 0). Es: [32 j][112] padded (t*28+v, pads = bias).
__global__ __launch_bounds__(256) void k1_emb_adj(
    const float* __restrict__ x,  const float* __restrict__ Wa, const float* __restrict__ ba,
    const float* __restrict__ Wb, const float* __restrict__ bb)
{
    extern __shared__ float sm1[];
    float* Xs  = sm1;             // 7168
    float* Es  = sm1 + 7168;      // 3584
    float* Wt3 = sm1 + 10752;     // 6912: [s][c][36-pad j]
    float* bs3 = sm1 + 17664;     // 96

    const int tid = threadIdx.x;
    const int n   = blockIdx.y;

    // stage all weights once (transposed for float4 loads over j)
    for (int i = tid; i < 6144; i += 256) {
        int s = i >> 11, r = i & 2047, j = r >> 6, c = r & 63;
        float w = (j < 16) ? Wa[(s*16 + j)*64 + c] : Wb[(s*16 + (j-16))*64 + c];
        Wt3[(s*64 + c)*36 + j] = w;
    }
    if (tid < 96) {
        int s = tid / 32, j = tid % 32;
        bs3[tid] = (j < 16) ? ba[s*16 + j] : bb[s*16 + (j-16)];
    }
    // zero Xs pad columns once (loader never touches them)
    for (int i = tid; i < 768; i += 256) {
        int c = i / 12, r = i - c*12, tt = r / 3, k = r - tt*3;
        Xs[c*112 + tt*28 + 25 + k] = 0.f;
    }

    // A1 accumulators as packed pairs
    ull accX[SS], accY2[SS];
    #pragma unroll
    for (int s = 0; s < SS; ++s) { accX[s] = 0ULL; accY2[s] = 0ULL; }
    const bool hasA = tid < 175;
    const int  vA = tid / 7, w4A = tid % 7;

    // embedding mapping: 224 threads = 8 jg x 28 (t, v4)
    const bool hasE = tid < 224;
    const int  jg = tid / 28, rE = tid % 28;
    const int  tE = rE / 7, v4E = rE % 7;

    __syncthreads();

    for (int sub = 0; sub < 8; ++sub) {
        const int tile = blockIdx.x * 8 + sub;
        __syncthreads();   // prev readers of Xs/Es done
        {   // load X tile into padded layout (float4 load, scalar scatter)
            const float4* xg = (const float4*)x;
            for (int i = tid; i < 1600; i += 256) {
                int c = i / 25, qq = i - c*25;
                float4 v4 = xg[(n*64 + c)*1600 + tile*25 + qq];
                int j = qq*4;
                float vals[4] = {v4.x, v4.y, v4.z, v4.w};
                #pragma unroll
                for (int k = 0; k < 4; ++k) {
                    int tt = (j+k) / 25, v = (j+k) - tt*25;
                    Xs[c*112 + tt*28 + v] = vals[k];
                }
            }
        }
        __syncthreads();

        for (int s = 0; s < SS; ++s) {
            // embeddings: each thread computes one (t, v4) quad for 4 j's
            if (hasE) {
                const ulonglong2* Xs2 = (const ulonglong2*)Xs;
                const float* wb_ = Wt3 + s*64*36;
                const float* bsp = bs3 + s*32 + jg*4;
                ull a0x = pack2(bsp[0]), a0y = a0x;
                ull a1x = pack2(bsp[1]), a1y = a1x;
                ull a2x = pack2(bsp[2]), a2y = a2x;
                ull a3x = pack2(bsp[3]), a3y = a3x;
                const int xo = tE*7 + v4E;
                #pragma unroll 8
                for (int c = 0; c < 64; ++c) {
                    float4 wv = *(const float4*)(wb_ + c*36 + jg*4);
                    ulonglong2 xv = Xs2[c*28 + xo];
                    ull w0 = pack2(wv.x), w1 = pack2(wv.y), w2 = pack2(wv.z), w3 = pack2(wv.w);
                    fma2(a0x, w0, xv.x); fma2(a0y, w0, xv.y);
                    fma2(a1x, w1, xv.x); fma2(a1y, w1, xv.y);
                    fma2(a2x, w2, xv.x); fma2(a2y, w2, xv.y);
                    fma2(a3x, w3, xv.x); fma2(a3y, w3, xv.y);
                }
                ulonglong2* Es2 = (ulonglong2*)Es;
                Es2[(jg*4+0)*28 + xo] = make_ulonglong2(a0x, a0y);
                Es2[(jg*4+1)*28 + xo] = make_ulonglong2(a1x, a1y);
                Es2[(jg*4+2)*28 + xo] = make_ulonglong2(a2x, a2y);
                Es2[(jg*4+3)*28 + xo] = make_ulonglong2(a3x, a3y);
            }
            __syncthreads();

            // A1 partial: vectorized b loads (LDS.128), packed fma
            if (hasA) {
                ull cx = accX[s], cy = accY2[s];
                const ulonglong2* Es2 = (const ulonglong2*)Es;
                #pragma unroll 4
                for (int j = 0; j < 16; ++j) {
                    #pragma unroll
                    for (int t = 0; t < 4; ++t) {
                        ull av = pack2(Es[j*112 + t*28 + vA]);
                        ulonglong2 br = Es2[(16+j)*28 + t*7 + w4A];
                        fma2(cx, av, br.x); fma2(cy, av, br.y);
                    }
                }
                accX[s] = cx; accY2[s] = cy;
            }
            __syncthreads();
        }
    }

    if (hasA) {
        #pragma unroll
        for (int s = 0; s < SS; ++s) {
            float2 f0 = unpack2(accX[s]), f1 = unpack2(accY2[s]);
            float vals[4] = {f0.x, f0.y, f1.x, f1.y};
            float* dst = &g_A1[((n*SS + s)*VV + vA)*VV];
            #pragma unroll
            for (int k = 0; k < 4; ++k) {
                int w = w4A*4 + k;
                if (w < VV) atomicAdd(&dst[w], vals[k]);
            }
        }
    }
}

// ---------------- K2 ----------------
__global__ void k2_adj(const float* __restrict__ PA, const float* __restrict__ alpha) {
    const float al = alpha[0];
    const int tot = NB*SS*VV*VV;
    for (int i = blockIdx.x*blockDim.x + threadIdx.x; i < tot; i += gridDim.x*blockDim.x)
        g_Ai[i] = PA[i % (SS*VV*VV)] + al * tanhf(g_A1[i] * (1.0f/4096.0f));
}

// ---------------- K3: fused (Wd@X)@Ai — o-major lanes, broadcast LDS ----------------
// grid (64, 64), 256 threads, dyn smem 48128 B, 3 blocks/SM target (84 regs)
__global__ __launch_bounds__(256, 3) void k3_main(
    const float* __restrict__ x,  const float* __restrict__ Wd, const float* __restrict__ bd,
    const float* __restrict__ gamma, const float* __restrict__ beta)
{
    extern __shared__ float sm[];
    float* Xs  = sm;            // 7168: [c][t*28+v] padded
    float* Ais = sm + 7168;     // 704:  [25][28] pad cols zeroed
    float* Wds = sm + 7872;     // 4160: [c][65-pad o]

    const int tid  = threadIdx.x;
    const int n    = blockIdx.y;
    const int tile = blockIdx.x;        // t0 = tile*4
    const int o    = tid & 63;
    const int t    = tid >> 6;

    if (tid < 25) { Ais[tid*28+25] = 0.f; Ais[tid*28+26] = 0.f; Ais[tid*28+27] = 0.f; }
    for (int i = tid; i < 768; i += 256) {
        int c = i / 12, r = i - c*12, tt = r / 3, k = r - tt*3;
        Xs[c*112 + tt*28 + 25 + k] = 0.f;
    }
    {
        const float4* xg = (const float4*)x;
        for (int i = tid; i < 1600; i += 256) {
            int c = i / 25, qq = i - c*25;
            float4 v4 = xg[(n*64 + c)*1600 + tile*25 + qq];
            int j = qq*4;
            float vals[4] = {v4.x, v4.y, v4.z, v4.w};
            #pragma unroll
            for (int k = 0; k < 4; ++k) {
                int tt = (j+k) / 25, v = (j+k) - tt*25;
                Xs[c*112 + tt*28 + v] = vals[k];
            }
        }
    }

    ull Y[14];
    #pragma unroll
    for (int k = 0; k < 14; ++k) Y[k] = 0ULL;

    for (int s = 0; s < SS; ++s) {
        __syncthreads();
        for (int i = tid; i < 625; i += 256) Ais[(i/25)*28 + (i%25)] = g_Ai[(n*SS + s)*625 + i];
        for (int i = tid; i < 4096; i += 256) {
            int oo = i >> 6, c = i & 63;
            Wds[c*65 + oo] = Wd[s*4096 + i];
        }
        __syncthreads();

        // stage 1: U[v] = sum_c Wd[o][c] * X[c][t][v] (X = warp-broadcast loads)
        ull U[14];
        #pragma unroll
        for (int k = 0; k < 14; ++k) U[k] = 0ULL;
        {
            const float* xb = Xs + t*28;
            #pragma unroll 4
            for (int c = 0; c < 64; ++c) {
                ull wp = pack2(Wds[c*65 + o]);
                const ulonglong2* xp = (const ulonglong2*)(xb + c*112);
                #pragma unroll
                for (int w4 = 0; w4 < 7; ++w4) {
                    ulonglong2 xv = xp[w4];
                    fma2(U[2*w4], wp, xv.x); fma2(U[2*w4+1], wp, xv.y);
                }
            }
        }

        // stage 2: Y[w] += sum_v U[v] * Ai[v][w] (Ai rows = broadcast)
        #pragma unroll
        for (int v = 0; v < 25; ++v) {
            float2 fu = unpack2(U[v >> 1]);
            ull uv = pack2((v & 1) ? fu.y : fu.x);
            const ulonglong2* ap = (const ulonglong2*)(Ais + v*28);
            #pragma unroll
            for (int w4 = 0; w4 < 7; ++w4) {
                ulonglong2 av = ap[w4];
                fma2(Y[2*w4], uv, av.x); fma2(Y[2*w4+1], uv, av.y);
            }
        }
    }

    // epilogue: bias + BN + residual + relu
    float yv[28];
    #pragma unroll
    for (int k = 0; k < 14; ++k) {
        float2 f = unpack2(Y[k]); yv[2*k] = f.x; yv[2*k+1] = f.y;
    }
    {
        const float scl  = rsqrtf(1.0f + 1e-5f);
        const float bsum = bd[o] + bd[64+o] + bd[128+o];
        const float scv  = gamma[o]*scl;
        const float btv  = beta[o];
        const float* xr = Xs + o*112 + t*28;
        #pragma unroll
        for (int w = 0; w < 25; ++w)
            yv[w] = fmaxf((yv[w] + bsum)*scv + btv + xr[w], 0.f);
    }
    __syncthreads();
    #pragma unroll
    for (int w = 0; w < 25; ++w) Xs[o*100 + t*25 + w] = yv[w];
    __syncthreads();

    {
        float4* yg = (float4*)g_y0;
        const float4* Xs4 = (const float4*)Xs;
        for (int i = tid; i < 1600; i += 256) {
            int c = i / 25, qq = i - c*25;
            yg[(n*64 + c)*1600 + tile*25 + qq] = Xs4[c*25 + qq];
        }
        for (int i = tid; i < 1600; i += 256) {
            int c = i / 25, v = i - c*25;
            float ssum = Xs[c*100 + v] + Xs[c*100 + 25 + v]
                       + Xs[c*100 + 50 + v] + Xs[c*100 + 75 + v];
            atomicAdd(&g_ST[n*1600 + i], ssum);
        }
    }
}

// ---------------- K4: spatial gate ----------------
__global__ __launch_bounds__(128) void k4_sgate(const float* __restrict__ Wsa,
                                                const float* __restrict__ bsa)
{
    __shared__ float se[1600];
    __shared__ float wk[1600];
    const int tid = threadIdx.x, n = blockIdx.x;
    for (int i = tid; i < 1600; i += 128) {
        se[i] = g_ST[n*1600 + i] * (1.0f/256.0f);
        wk[i] = Wsa[i];
    }
    __syncthreads();
    if (tid < VV) {
        int v = tid;
        float acc = bsa[0];
        for (int c = 0; c < 64; ++c)
            #pragma unroll
            for (int k = 0; k < 25; ++k) {
                int u = v + k - 12;
                if (u >= 0 && u < 25) acc += wk[c*25 + k] * se[c*25 + u];
            }
        g_gs[n*25 + v] = 1.0f + sigm(acc);
    }
}

// ---------------- K5: SVw = sum_v y0*(1+gs) ----------------
__global__ __launch_bounds__(256) void k5_svw() {
    __shared__ float gs[25];
    const int c = blockIdx.x, n = blockIdx.y, t = threadIdx.x;
    if (t < 25) gs[t] = g_gs[n*25 + t];
    __syncthreads();
    const float* row = &g_y0[((n*64 + c)*256 + t)*25];
    float s = 0.f;
    #pragma unroll
    for (int v = 0; v < 25; ++v) s += row[v] * gs[v];
    g_SVw[(n*64 + c)*256 + t] = s;
}

// ---------------- K6: temporal gate ----------------
__global__ __launch_bounds__(256) void k6_tgate(const float* __restrict__ Wta,
                                                const float* __restrict__ bta)
{
    __shared__ float wk[576];
    const int tid = threadIdx.x, n = blockIdx.x;
    for (int i = tid; i < 576; i += 256) wk[i] = Wta[i];
    __syncthreads();
    const int t = tid;
    float s = 0.f;
    for (int c = 0; c < 64; ++c) {
        const float* sv = &g_SVw[(n*64 + c)*256];
        #pragma unroll
        for (int k = 0; k < 9; ++k) {
            int u = t + k - 4;
            if (u >= 0 && u < 256) s += wk[c*9 + k] * sv[u];
        }
    }
    float acc = bta[0] + s * (1.0f/25.0f);
    g_gt[n*256 + t] = 1.0f + sigm(acc);
}

// ---------------- K7: channel gate ----------------
__global__ __launch_bounds__(64) void k7_cgate(
    const float* __restrict__ W1, const float* __restrict__ b1,
    const float* __restrict__ W2, const float* __restrict__ b2)
{
    __shared__ float gt[256];
    __shared__ float se[64];
    __shared__ float h[32];
    const int tid = threadIdx.x, n = blockIdx.x;
    for (int i = tid; i < 256; i += 64) gt[i] = g_gt[n*256 + i];
    __syncthreads();
    {
        const float* sv = &g_SVw[(n*64 + tid)*256];
        float s = 0.f;
        for (int t = 0; t < 256; ++t) s += sv[t] * gt[t];
        se[tid] = s * (1.0f/6400.0f);
    }
    __syncthreads();
    if (tid < 32) {
        float a = b1[tid];
        for (int c = 0; c < 64; ++c) a += W1[tid*64 + c] * se[c];
        h[tid] = fmaxf(a, 0.f);
    }
    __syncthreads();
    {
        float a = b2[tid];
        #pragma unroll
        for (int j = 0; j < 32; ++j) a += W2[tid*32 + j] * h[j];
        g_gc[n*64 + tid] = 1.0f + sigm(a);
    }
}

// ---------------- K8: finalize ----------------
__global__ __launch_bounds__(256) void k8_final(float* __restrict__ out) {
    const int i4 = blockIdx.x*256 + threadIdx.x;
    if (i4 >= NB*CC*TT*VV/4) return;
    float4 y = ((const float4*)g_y0)[i4];
    float r[4] = {y.x, y.y, y.z, y.w};
    #pragma unroll
    for (int k = 0; k < 4; ++k) {
        unsigned idx = (unsigned)i4*4u + k;
        unsigned row = idx / 25u;
        unsigned v   = idx - row*25u;
        unsigned t   = row & 255u;
        unsigned nc  = row >> 8;
        unsigned n   = nc >> 6;
        r[k] *= g_gs[n*25 + v] * g_gt[n*256 + t] * g_gc[nc];
    }
    ((float4*)out)[i4] = make_float4(r[0], r[1], r[2], r[3]);
}

// ---------------- launch ----------------
extern "C" void kernel_launch(void* const* d_in, const int* in_sizes, int n_in,
                              void* d_out, int out_size) {
    const float* x     = (const float*)d_in[0];
    const float* PA    = (const float*)d_in[1];
    const float* alpha = (const float*)d_in[2];
    const float* Wa    = (const float*)d_in[3];
    const float* ba    = (const float*)d_in[4];
    const float* Wb    = (const float*)d_in[5];
    const float* bb    = (const float*)d_in[6];
    const float* Wd    = (const float*)d_in[7];
    const float* bd    = (const float*)d_in[8];
    const float* gam   = (const float*)d_in[9];
    const float* bet   = (const float*)d_in[10];
    const float* Wsa   = (const float*)d_in[11];
    const float* bsa   = (const float*)d_in[12];
    const float* Wta   = (const float*)d_in[13];
    const float* bta   = (const float*)d_in[14];
    const float* W1    = (const float*)d_in[15];
    const float* b1    = (const float*)d_in[16];
    const float* W2    = (const float*)d_in[17];
    const float* b2    = (const float*)d_in[18];
    float* out = (float*)d_out;

    cudaFuncSetAttribute(k1_emb_adj, cudaFuncAttributeMaxDynamicSharedMemorySize, 71680);
    cudaFuncSetAttribute(k3_main,    cudaFuncAttributeMaxDynamicSharedMemorySize, 49152);

    k0_zero<<<224, 1024>>>();
    k1_emb_adj<<<dim3(8, 64), 256, 71040>>>(x, Wa, ba, Wb, bb);
    k2_adj<<<120, 1024>>>(PA, alpha);
    k3_main<<<dim3(64, 64), 256, 48128>>>(x, Wd, bd, gam, bet);
    k4_sgate<<<64, 128>>>(Wsa, bsa);
    k5_svw<<<dim3(64, 64), 256>>>();
    k6_tgate<<<64, 256>>>(Wta, bta);
    k7_cgate<<<64, 64>>>(W1, b1, W2, b2);
    k8_final<<<25600, 256>>>(out);
}

// round 13
// speedup vs baseline: 1.7407x; 1.1289x over previous
#include <cuda_runtime.h>
#include <math.h>

#define NB 64
#define CC 64
#define TT 256
#define VV 25
#define SS 3
#define II 16

typedef unsigned long long ull;

// ---------------- device scratch ----------------
__device__ float g_A1 [NB*SS*VV*VV];
__device__ float g_Ai [NB*SS*VV*VV];
__device__ float g_y0 [NB*CC*TT*VV];   // ~105MB
__device__ float g_ST [NB*CC*VV];
__device__ float g_SVw[NB*CC*TT];
__device__ float g_gs [NB*VV];
__device__ float g_gt [NB*TT];
__device__ float g_gc [NB*CC];

__device__ __forceinline__ float sigm(float x) { return 1.0f / (1.0f + expf(-x)); }

// packed fp32x2 helpers
__device__ __forceinline__ ull pack2(float f) {
    ull r;
    asm("mov.b64 %0, {%1, %1};" : "=l"(r) : "r"(__float_as_uint(f)));
    return r;
}
__device__ __forceinline__ void fma2(ull& d, ull a, ull b) {
    asm("fma.rn.f32x2 %0, %1, %2, %0;" : "+l"(d) : "l"(a), "l"(b));
}
__device__ __forceinline__ float2 unpack2(ull p) {
    unsigned lo, hi;
    asm("mov.b64 {%0, %1}, %2;" : "=r"(lo), "=r"(hi) : "l"(p));
    return make_float2(__uint_as_float(lo), __uint_as_float(hi));
}

// ---------------- K0 ----------------
__global__ void k0_zero() {
    const int tot = NB*SS*VV*VV + NB*CC*VV;
    for (int i = blockIdx.x*blockDim.x + threadIdx.x; i < tot; i += gridDim.x*blockDim.x) {
        if (i < NB*SS*VV*VV) g_A1[i] = 0.f;
        else                 g_ST[i - NB*SS*VV*VV] = 0.f;
    }
}

// ---------------- K1: embeddings + partial A1 (padded layouts) ----------------
// grid (8, 64), 256 threads, dyn smem 71040 B
__global__ __launch_bounds__(256) void k1_emb_adj(
    const float* __restrict__ x,  const float* __restrict__ Wa, const float* __restrict__ ba,
    const float* __restrict__ Wb, const float* __restrict__ bb)
{
    extern __shared__ float sm1[];
    float* Xs  = sm1;             // 7168
    float* Es  = sm1 + 7168;      // 3584
    float* Wt3 = sm1 + 10752;     // 6912: [s][c][36-pad j]
    float* bs3 = sm1 + 17664;     // 96

    const int tid = threadIdx.x;
    const int n   = blockIdx.y;

    for (int i = tid; i < 6144; i += 256) {
        int s = i >> 11, r = i & 2047, j = r >> 6, c = r & 63;
        float w = (j < 16) ? Wa[(s*16 + j)*64 + c] : Wb[(s*16 + (j-16))*64 + c];
        Wt3[(s*64 + c)*36 + j] = w;
    }
    if (tid < 96) {
        int s = tid / 32, j = tid % 32;
        bs3[tid] = (j < 16) ? ba[s*16 + j] : bb[s*16 + (j-16)];
    }
    for (int i = tid; i < 768; i += 256) {
        int c = i / 12, r = i - c*12, tt = r / 3, k = r - tt*3;
        Xs[c*112 + tt*28 + 25 + k] = 0.f;
    }

    ull accX[SS], accY2[SS];
    #pragma unroll
    for (int s = 0; s < SS; ++s) { accX[s] = 0ULL; accY2[s] = 0ULL; }
    const bool hasA = tid < 175;
    const int  vA = tid / 7, w4A = tid % 7;

    const bool hasE = tid < 224;
    const int  jg = tid / 28, rE = tid % 28;
    const int  tE = rE / 7, v4E = rE % 7;

    __syncthreads();

    for (int sub = 0; sub < 8; ++sub) {
        const int tile = blockIdx.x * 8 + sub;
        __syncthreads();
        {
            const float4* xg = (const float4*)x;
            for (int i = tid; i < 1600; i += 256) {
                int c = i / 25, qq = i - c*25;
                float4 v4 = xg[(n*64 + c)*1600 + tile*25 + qq];
                int j = qq*4;
                float vals[4] = {v4.x, v4.y, v4.z, v4.w};
                #pragma unroll
                for (int k = 0; k < 4; ++k) {
                    int tt = (j+k) / 25, v = (j+k) - tt*25;
                    Xs[c*112 + tt*28 + v] = vals[k];
                }
            }
        }
        __syncthreads();

        for (int s = 0; s < SS; ++s) {
            if (hasE) {
                const ulonglong2* Xs2 = (const ulonglong2*)Xs;
                const float* wb_ = Wt3 + s*64*36;
                const float* bsp = bs3 + s*32 + jg*4;
                ull a0x = pack2(bsp[0]), a0y = a0x;
                ull a1x = pack2(bsp[1]), a1y = a1x;
                ull a2x = pack2(bsp[2]), a2y = a2x;
                ull a3x = pack2(bsp[3]), a3y = a3x;
                const int xo = tE*7 + v4E;
                #pragma unroll 8
                for (int c = 0; c < 64; ++c) {
                    float4 wv = *(const float4*)(wb_ + c*36 + jg*4);
                    ulonglong2 xv = Xs2[c*28 + xo];
                    ull w0 = pack2(wv.x), w1 = pack2(wv.y), w2 = pack2(wv.z), w3 = pack2(wv.w);
                    fma2(a0x, w0, xv.x); fma2(a0y, w0, xv.y);
                    fma2(a1x, w1, xv.x); fma2(a1y, w1, xv.y);
                    fma2(a2x, w2, xv.x); fma2(a2y, w2, xv.y);
                    fma2(a3x, w3, xv.x); fma2(a3y, w3, xv.y);
                }
                ulonglong2* Es2 = (ulonglong2*)Es;
                Es2[(jg*4+0)*28 + xo] = make_ulonglong2(a0x, a0y);
                Es2[(jg*4+1)*28 + xo] = make_ulonglong2(a1x, a1y);
                Es2[(jg*4+2)*28 + xo] = make_ulonglong2(a2x, a2y);
                Es2[(jg*4+3)*28 + xo] = make_ulonglong2(a3x, a3y);
            }
            __syncthreads();

            if (hasA) {
                ull cx = accX[s], cy = accY2[s];
                const ulonglong2* Es2 = (const ulonglong2*)Es;
                #pragma unroll 4
                for (int j = 0; j < 16; ++j) {
                    #pragma unroll
                    for (int t = 0; t < 4; ++t) {
                        ull av = pack2(Es[j*112 + t*28 + vA]);
                        ulonglong2 br = Es2[(16+j)*28 + t*7 + w4A];
                        fma2(cx, av, br.x); fma2(cy, av, br.y);
                    }
                }
                accX[s] = cx; accY2[s] = cy;
            }
            __syncthreads();
        }
    }

    if (hasA) {
        #pragma unroll
        for (int s = 0; s < SS; ++s) {
            float2 f0 = unpack2(accX[s]), f1 = unpack2(accY2[s]);
            float vals[4] = {f0.x, f0.y, f1.x, f1.y};
            float* dst = &g_A1[((n*SS + s)*VV + vA)*VV];
            #pragma unroll
            for (int k = 0; k < 4; ++k) {
                int w = w4A*4 + k;
                if (w < VV) atomicAdd(&dst[w], vals[k]);
            }
        }
    }
}

// ---------------- K2 ----------------
__global__ void k2_adj(const float* __restrict__ PA, const float* __restrict__ alpha) {
    const float al = alpha[0];
    const int tot = NB*SS*VV*VV;
    for (int i = blockIdx.x*blockDim.x + threadIdx.x; i < tot; i += gridDim.x*blockDim.x)
        g_Ai[i] = PA[i % (SS*VV*VV)] + al * tanhf(g_A1[i] * (1.0f/4096.0f));
}

// ---------------- K3: fused (Wd@X)@Ai — o-PAIR per thread, halved LDS wavefronts ----
// grid (64, 64), 128 threads, dyn smem 48128 B, 3 blocks/SM
// thread = (o0 = lane, o1 = lane+32, t = warp 0..3). X/Ai loads shared by both o's.
__global__ __launch_bounds__(128, 3) void k3_main(
    const float* __restrict__ x,  const float* __restrict__ Wd, const float* __restrict__ bd,
    const float* __restrict__ gamma, const float* __restrict__ beta)
{
    extern __shared__ float sm[];
    float* Xs  = sm;            // 7168: [c][t*28+v] padded
    float* Ais = sm + 7168;     // 704:  [25][28] pad cols zeroed
    float* Wds = sm + 7872;     // 4160: [c][65-pad o]

    const int tid  = threadIdx.x;
    const int n    = blockIdx.y;
    const int tile = blockIdx.x;        // t0 = tile*4
    const int o0   = tid & 31;
    const int o1   = o0 + 32;
    const int t    = tid >> 5;          // one t per warp

    if (tid < 25) { Ais[tid*28+25] = 0.f; Ais[tid*28+26] = 0.f; Ais[tid*28+27] = 0.f; }
    for (int i = tid; i < 768; i += 128) {
        int c = i / 12, r = i - c*12, tt = r / 3, k = r - tt*3;
        Xs[c*112 + tt*28 + 25 + k] = 0.f;
    }
    {
        const float4* xg = (const float4*)x;
        for (int i = tid; i < 1600; i += 128) {
            int c = i / 25, qq = i - c*25;
            float4 v4 = xg[(n*64 + c)*1600 + tile*25 + qq];
            int j = qq*4;
            float vals[4] = {v4.x, v4.y, v4.z, v4.w};
            #pragma unroll
            for (int k = 0; k < 4; ++k) {
                int tt = (j+k) / 25, v = (j+k) - tt*25;
                Xs[c*112 + tt*28 + v] = vals[k];
            }
        }
    }

    ull Y0[14], Y1[14];
    #pragma unroll
    for (int k = 0; k < 14; ++k) { Y0[k] = 0ULL; Y1[k] = 0ULL; }

    for (int s = 0; s < SS; ++s) {
        __syncthreads();
        for (int i = tid; i < 625; i += 128) Ais[(i/25)*28 + (i%25)] = g_Ai[(n*SS + s)*625 + i];
        for (int i = tid; i < 4096; i += 128) {
            int oo = i >> 6, c = i & 63;
            Wds[c*65 + oo] = Wd[s*4096 + i];
        }
        __syncthreads();

        // stage 1: U{0,1}[v] = sum_c Wd[o{0,1}][c] * X[c][t][v]; X loads shared
        ull U0[14], U1[14];
        #pragma unroll
        for (int k = 0; k < 14; ++k) { U0[k] = 0ULL; U1[k] = 0ULL; }
        {
            const float* xb = Xs + t*28;
            #pragma unroll 2
            for (int c = 0; c < 64; ++c) {
                ull w0 = pack2(Wds[c*65 + o0]);
                ull w1 = pack2(Wds[c*65 + o1]);
                const ulonglong2* xp = (const ulonglong2*)(xb + c*112);
                #pragma unroll
                for (int w4 = 0; w4 < 7; ++w4) {
                    ulonglong2 xv = xp[w4];
                    fma2(U0[2*w4], w0, xv.x); fma2(U0[2*w4+1], w0, xv.y);
                    fma2(U1[2*w4], w1, xv.x); fma2(U1[2*w4+1], w1, xv.y);
                }
            }
        }

        // stage 2: Y{0,1}[w] += sum_v U{0,1}[v] * Ai[v][w]; Ai loads shared
        #pragma unroll
        for (int v = 0; v < 25; ++v) {
            float2 fu0 = unpack2(U0[v >> 1]);
            float2 fu1 = unpack2(U1[v >> 1]);
            ull uv0 = pack2((v & 1) ? fu0.y : fu0.x);
            ull uv1 = pack2((v & 1) ? fu1.y : fu1.x);
            const ulonglong2* ap = (const ulonglong2*)(Ais + v*28);
            #pragma unroll
            for (int w4 = 0; w4 < 7; ++w4) {
                ulonglong2 av = ap[w4];
                fma2(Y0[2*w4], uv0, av.x); fma2(Y0[2*w4+1], uv0, av.y);
                fma2(Y1[2*w4], uv1, av.x); fma2(Y1[2*w4+1], uv1, av.y);
            }
        }
    }

    // epilogue: bias + BN + residual + relu for both o's
    float ya[28], yb[28];
    #pragma unroll
    for (int k = 0; k < 14; ++k) {
        float2 f0 = unpack2(Y0[k]); ya[2*k] = f0.x; ya[2*k+1] = f0.y;
        float2 f1 = unpack2(Y1[k]); yb[2*k] = f1.x; yb[2*k+1] = f1.y;
    }
    {
        const float scl  = rsqrtf(1.0f + 1e-5f);
        const float bsA = bd[o0] + bd[64+o0] + bd[128+o0];
        const float bsB = bd[o1] + bd[64+o1] + bd[128+o1];
        const float scA = gamma[o0]*scl, scB = gamma[o1]*scl;
        const float btA = beta[o0],      btB = beta[o1];
        const float* xrA = Xs + o0*112 + t*28;
        const float* xrB = Xs + o1*112 + t*28;
        #pragma unroll
        for (int w = 0; w < 25; ++w) {
            ya[w] = fmaxf((ya[w] + bsA)*scA + btA + xrA[w], 0.f);
            yb[w] = fmaxf((yb[w] + bsB)*scB + btB + xrB[w], 0.f);
        }
    }
    __syncthreads();
    #pragma unroll
    for (int w = 0; w < 25; ++w) {
        Xs[o0*100 + t*25 + w] = ya[w];
        Xs[o1*100 + t*25 + w] = yb[w];
    }
    __syncthreads();

    {
        float4* yg = (float4*)g_y0;
        const float4* Xs4 = (const float4*)Xs;
        for (int i = tid; i < 1600; i += 128) {
            int c = i / 25, qq = i - c*25;
            yg[(n*64 + c)*1600 + tile*25 + qq] = Xs4[c*25 + qq];
        }
        for (int i = tid; i < 1600; i += 128) {
            int c = i / 25, v = i - c*25;
            float ssum = Xs[c*100 + v] + Xs[c*100 + 25 + v]
                       + Xs[c*100 + 50 + v] + Xs[c*100 + 75 + v];
            atomicAdd(&g_ST[n*1600 + i], ssum);
        }
    }
}

// ---------------- K4: spatial gate ----------------
__global__ __launch_bounds__(128) void k4_sgate(const float* __restrict__ Wsa,
                                                const float* __restrict__ bsa)
{
    __shared__ float se[1600];
    __shared__ float wk[1600];
    const int tid = threadIdx.x, n = blockIdx.x;
    for (int i = tid; i < 1600; i += 128) {
        se[i] = g_ST[n*1600 + i] * (1.0f/256.0f);
        wk[i] = Wsa[i];
    }
    __syncthreads();
    if (tid < VV) {
        int v = tid;
        float acc = bsa[0];
        for (int c = 0; c < 64; ++c)
            #pragma unroll
            for (int k = 0; k < 25; ++k) {
                int u = v + k - 12;
                if (u >= 0 && u < 25) acc += wk[c*25 + k] * se[c*25 + u];
            }
        g_gs[n*25 + v] = 1.0f + sigm(acc);
    }
}

// ---------------- K5: SVw = sum_v y0*(1+gs) ----------------
__global__ __launch_bounds__(256) void k5_svw() {
    __shared__ float gs[25];
    const int c = blockIdx.x, n = blockIdx.y, t = threadIdx.x;
    if (t < 25) gs[t] = g_gs[n*25 + t];
    __syncthreads();
    const float* row = &g_y0[((n*64 + c)*256 + t)*25];
    float s = 0.f;
    #pragma unroll
    for (int v = 0; v < 25; ++v) s += row[v] * gs[v];
    g_SVw[(n*64 + c)*256 + t] = s;
}

// ---------------- K6: temporal gate ----------------
__global__ __launch_bounds__(256) void k6_tgate(const float* __restrict__ Wta,
                                                const float* __restrict__ bta)
{
    __shared__ float wk[576];
    const int tid = threadIdx.x, n = blockIdx.x;
    for (int i = tid; i < 576; i += 256) wk[i] = Wta[i];
    __syncthreads();
    const int t = tid;
    float s = 0.f;
    for (int c = 0; c < 64; ++c) {
        const float* sv = &g_SVw[(n*64 + c)*256];
        #pragma unroll
        for (int k = 0; k < 9; ++k) {
            int u = t + k - 4;
            if (u >= 0 && u < 256) s += wk[c*9 + k] * sv[u];
        }
    }
    float acc = bta[0] + s * (1.0f/25.0f);
    g_gt[n*256 + t] = 1.0f + sigm(acc);
}

// ---------------- K7: channel gate ----------------
__global__ __launch_bounds__(64) void k7_cgate(
    const float* __restrict__ W1, const float* __restrict__ b1,
    const float* __restrict__ W2, const float* __restrict__ b2)
{
    __shared__ float gt[256];
    __shared__ float se[64];
    __shared__ float h[32];
    const int tid = threadIdx.x, n = blockIdx.x;
    for (int i = tid; i < 256; i += 64) gt[i] = g_gt[n*256 + i];
    __syncthreads();
    {
        const float* sv = &g_SVw[(n*64 + tid)*256];
        float s = 0.f;
        for (int t = 0; t < 256; ++t) s += sv[t] * gt[t];
        se[tid] = s * (1.0f/6400.0f);
    }
    __syncthreads();
    if (tid < 32) {
        float a = b1[tid];
        for (int c = 0; c < 64; ++c) a += W1[tid*64 + c] * se[c];
        h[tid] = fmaxf(a, 0.f);
    }
    __syncthreads();
    {
        float a = b2[tid];
        #pragma unroll
        for (int j = 0; j < 32; ++j) a += W2[tid*32 + j] * h[j];
        g_gc[n*64 + tid] = 1.0f + sigm(a);
    }
}

// ---------------- K8: finalize ----------------
__global__ __launch_bounds__(256) void k8_final(float* __restrict__ out) {
    const int i4 = blockIdx.x*256 + threadIdx.x;
    if (i4 >= NB*CC*TT*VV/4) return;
    float4 y = ((const float4*)g_y0)[i4];
    float r[4] = {y.x, y.y, y.z, y.w};
    #pragma unroll
    for (int k = 0; k < 4; ++k) {
        unsigned idx = (unsigned)i4*4u + k;
        unsigned row = idx / 25u;
        unsigned v   = idx - row*25u;
        unsigned t   = row & 255u;
        unsigned nc  = row >> 8;
        unsigned n   = nc >> 6;
        r[k] *= g_gs[n*25 + v] * g_gt[n*256 + t] * g_gc[nc];
    }
    ((float4*)out)[i4] = make_float4(r[0], r[1], r[2], r[3]);
}

// ---------------- launch ----------------
extern "C" void kernel_launch(void* const* d_in, const int* in_sizes, int n_in,
                              void* d_out, int out_size) {
    const float* x     = (const float*)d_in[0];
    const float* PA    = (const float*)d_in[1];
    const float* alpha = (const float*)d_in[2];
    const float* Wa    = (const float*)d_in[3];
    const float* ba    = (const float*)d_in[4];
    const float* Wb    = (const float*)d_in[5];
    const float* bb    = (const float*)d_in[6];
    const float* Wd    = (const float*)d_in[7];
    const float* bd    = (const float*)d_in[8];
    const float* gam   = (const float*)d_in[9];
    const float* bet   = (const float*)d_in[10];
    const float* Wsa   = (const float*)d_in[11];
    const float* bsa   = (const float*)d_in[12];
    const float* Wta   = (const float*)d_in[13];
    const float* bta   = (const float*)d_in[14];
    const float* W1    = (const float*)d_in[15];
    const float* b1    = (const float*)d_in[16];
    const float* W2    = (const float*)d_in[17];
    const float* b2    = (const float*)d_in[18];
    float* out = (float*)d_out;

    cudaFuncSetAttribute(k1_emb_adj, cudaFuncAttributeMaxDynamicSharedMemorySize, 71680);
    cudaFuncSetAttribute(k3_main,    cudaFuncAttributeMaxDynamicSharedMemorySize, 49152);

    k0_zero<<<224, 1024>>>();
    k1_emb_adj<<<dim3(8, 64), 256, 71040>>>(x, Wa, ba, Wb, bb);
    k2_adj<<<120, 1024>>>(PA, alpha);
    k3_main<<<dim3(64, 64), 128, 48128>>>(x, Wd, bd, gam, bet);
    k4_sgate<<<64, 128>>>(Wsa, bsa);
    k5_svw<<<dim3(64, 64), 256>>>();
    k6_tgate<<<64, 256>>>(Wta, bta);
    k7_cgate<<<64, 64>>>(W1, b1, W2, b2);
    k8_final<<<25600, 256>>>(out);
}

// round 14
// speedup vs baseline: 1.7589x; 1.0105x over previous
#include <cuda_runtime.h>
#include <math.h>

#define NB 64
#define CC 64
#define TT 256
#define VV 25
#define SS 3
#define II 16

typedef unsigned long long ull;

// ---------------- device scratch ----------------
__device__ float g_A1 [NB*SS*VV*VV];
__device__ float g_Ai [NB*SS*VV*VV];
__device__ float g_y0 [NB*CC*TT*VV];   // ~105MB
__device__ float g_ST [NB*CC*VV];
__device__ float g_SVw[NB*CC*TT];
__device__ float g_gs [NB*VV];
__device__ float g_gt [NB*TT];
__device__ float g_gc [NB*CC];

__device__ __forceinline__ float sigm(float x) { return 1.0f / (1.0f + expf(-x)); }

// packed fp32x2 helpers
__device__ __forceinline__ ull pack2(float f) {
    ull r;
    asm("mov.b64 %0, {%1, %1};" : "=l"(r) : "r"(__float_as_uint(f)));
    return r;
}
__device__ __forceinline__ void fma2(ull& d, ull a, ull b) {
    asm("fma.rn.f32x2 %0, %1, %2, %0;" : "+l"(d) : "l"(a), "l"(b));
}
__device__ __forceinline__ float2 unpack2(ull p) {
    unsigned lo, hi;
    asm("mov.b64 {%0, %1}, %2;" : "=r"(lo), "=r"(hi) : "l"(p));
    return make_float2(__uint_as_float(lo), __uint_as_float(hi));
}

// ---------------- K0 ----------------
__global__ void k0_zero() {
    const int tot = NB*SS*VV*VV + NB*CC*VV;
    for (int i = blockIdx.x*blockDim.x + threadIdx.x; i < tot; i += gridDim.x*blockDim.x) {
        if (i < NB*SS*VV*VV) g_A1[i] = 0.f;
        else                 g_ST[i - NB*SS*VV*VV] = 0.f;
    }
}

// ---------------- K1: embeddings + partial A1 — s-FUSED single pass ----------------
// grid (8, 64), 256 threads, dyn smem 99712 B
// Es: 96 rows (s*32 + j; j 0..15 = a, 16..31 = b), stride 112, padded layout t*28+v.
__global__ __launch_bounds__(256) void k1_emb_adj(
    const float* __restrict__ x,  const float* __restrict__ Wa, const float* __restrict__ ba,
    const float* __restrict__ Wb, const float* __restrict__ bb)
{
    extern __shared__ float sm1[];
    float* Xs  = sm1;             // 7168:  [c][112] padded (pads 0)
    float* Es  = sm1 + 7168;      // 10752: [96][112]
    float* Wt3 = sm1 + 17920;     // 6912:  [s][c][36-pad j]
    float* bs3 = sm1 + 24832;     // 96:    [s][32]

    const int tid = threadIdx.x;
    const int n   = blockIdx.y;

    // stage all weights once (transposed for float4 loads over j)
    for (int i = tid; i < 6144; i += 256) {
        int s = i >> 11, r = i & 2047, j = r >> 6, c = r & 63;
        float w = (j < 16) ? Wa[(s*16 + j)*64 + c] : Wb[(s*16 + (j-16))*64 + c];
        Wt3[(s*64 + c)*36 + j] = w;
    }
    if (tid < 96) {
        int s = tid / 32, j = tid % 32;
        bs3[tid] = (j < 16) ? ba[s*16 + j] : bb[s*16 + (j-16)];
    }
    // zero Xs pad columns (loader never touches them)
    for (int i = tid; i < 768; i += 256) {
        int c = i / 12, r = i - c*12, tt = r / 3, k = r - tt*3;
        Xs[c*112 + tt*28 + 25 + k] = 0.f;
    }

    // A1 accumulators (packed pairs) per s
    ull accX[SS], accY2[SS];
    #pragma unroll
    for (int s = 0; s < SS; ++s) { accX[s] = 0ULL; accY2[s] = 0ULL; }
    const bool hasA = tid < 175;
    const int  vA = tid / 7, w4A = tid % 7;

    // embedding mapping: 224 threads = 8 jg x 28 (t*7+v4)
    const bool hasE = tid < 224;
    const int  jg = tid / 28, xo = tid % 28;

    __syncthreads();

    for (int sub = 0; sub < 8; ++sub) {
        const int tile = blockIdx.x * 8 + sub;
        __syncthreads();   // prev A1 reads of Es + embed reads of Xs done
        {   // load X tile into padded layout
            const float4* xg = (const float4*)x;
            for (int i = tid; i < 1600; i += 256) {
                int c = i / 25, qq = i - c*25;
                float4 v4 = xg[(n*64 + c)*1600 + tile*25 + qq];
                int j = qq*4;
                float vals[4] = {v4.x, v4.y, v4.z, v4.w};
                #pragma unroll
                for (int k = 0; k < 4; ++k) {
                    int tt = (j+k) / 25, v = (j+k) - tt*25;
                    Xs[c*112 + tt*28 + v] = vals[k];
                }
            }
        }
        __syncthreads();

        // embeddings for ALL 3 s in one pass over c (X loaded once)
        if (hasE) {
            ull acc[SS][8];
            #pragma unroll
            for (int s = 0; s < SS; ++s) {
                const float* bsp = bs3 + s*32 + jg*4;
                #pragma unroll
                for (int k = 0; k < 4; ++k) {
                    ull b = pack2(bsp[k]);
                    acc[s][2*k] = b; acc[s][2*k+1] = b;
                }
            }
            const ulonglong2* Xs2 = (const ulonglong2*)Xs;
            #pragma unroll 4
            for (int c = 0; c < 64; ++c) {
                ulonglong2 xv = Xs2[c*28 + xo];
                #pragma unroll
                for (int s = 0; s < SS; ++s) {
                    float4 wv = *(const float4*)(Wt3 + (s*64 + c)*36 + jg*4);
                    ull w0 = pack2(wv.x), w1 = pack2(wv.y), w2 = pack2(wv.z), w3 = pack2(wv.w);
                    fma2(acc[s][0], w0, xv.x); fma2(acc[s][1], w0, xv.y);
                    fma2(acc[s][2], w1, xv.x); fma2(acc[s][3], w1, xv.y);
                    fma2(acc[s][4], w2, xv.x); fma2(acc[s][5], w2, xv.y);
                    fma2(acc[s][6], w3, xv.x); fma2(acc[s][7], w3, xv.y);
                }
            }
            ulonglong2* Es2 = (ulonglong2*)Es;
            #pragma unroll
            for (int s = 0; s < SS; ++s) {
                #pragma unroll
                for (int k = 0; k < 4; ++k)
                    Es2[(s*32 + jg*4 + k)*28 + xo] = make_ulonglong2(acc[s][2*k], acc[s][2*k+1]);
            }
        }
        __syncthreads();

        // A1 partial for all 3 s
        if (hasA) {
            #pragma unroll
            for (int s = 0; s < SS; ++s) {
                ull cx = accX[s], cy = accY2[s];
                const float* Ea = Es + (s*32)*112;
                const ulonglong2* Eb = (const ulonglong2*)(Es + (s*32 + 16)*112);
                #pragma unroll 4
                for (int j = 0; j < 16; ++j) {
                    #pragma unroll
                    for (int t = 0; t < 4; ++t) {
                        ull av = pack2(Ea[j*112 + t*28 + vA]);
                        ulonglong2 br = Eb[j*28 + t*7 + w4A];
                        fma2(cx, av, br.x); fma2(cy, av, br.y);
                    }
                }
                accX[s] = cx; accY2[s] = cy;
            }
        }
    }

    if (hasA) {
        #pragma unroll
        for (int s = 0; s < SS; ++s) {
            float2 f0 = unpack2(accX[s]), f1 = unpack2(accY2[s]);
            float vals[4] = {f0.x, f0.y, f1.x, f1.y};
            float* dst = &g_A1[((n*SS + s)*VV + vA)*VV];
            #pragma unroll
            for (int k = 0; k < 4; ++k) {
                int w = w4A*4 + k;
                if (w < VV) atomicAdd(&dst[w], vals[k]);
            }
        }
    }
}

// ---------------- K2 ----------------
__global__ void k2_adj(const float* __restrict__ PA, const float* __restrict__ alpha) {
    const float al = alpha[0];
    const int tot = NB*SS*VV*VV;
    for (int i = blockIdx.x*blockDim.x + threadIdx.x; i < tot; i += gridDim.x*blockDim.x)
        g_Ai[i] = PA[i % (SS*VV*VV)] + al * tanhf(g_A1[i] * (1.0f/4096.0f));
}

// ---------------- K3: fused (Wd@X)@Ai — o-PAIR per thread (unchanged from R12) ----
// grid (64, 64), 128 threads, dyn smem 48128 B, 3 blocks/SM
__global__ __launch_bounds__(128, 3) void k3_main(
    const float* __restrict__ x,  const float* __restrict__ Wd, const float* __restrict__ bd,
    const float* __restrict__ gamma, const float* __restrict__ beta)
{
    extern __shared__ float sm[];
    float* Xs  = sm;            // 7168: [c][t*28+v] padded
    float* Ais = sm + 7168;     // 704:  [25][28] pad cols zeroed
    float* Wds = sm + 7872;     // 4160: [c][65-pad o]

    const int tid  = threadIdx.x;
    const int n    = blockIdx.y;
    const int tile = blockIdx.x;        // t0 = tile*4
    const int o0   = tid & 31;
    const int o1   = o0 + 32;
    const int t    = tid >> 5;          // one t per warp

    if (tid < 25) { Ais[tid*28+25] = 0.f; Ais[tid*28+26] = 0.f; Ais[tid*28+27] = 0.f; }
    for (int i = tid; i < 768; i += 128) {
        int c = i / 12, r = i - c*12, tt = r / 3, k = r - tt*3;
        Xs[c*112 + tt*28 + 25 + k] = 0.f;
    }
    {
        const float4* xg = (const float4*)x;
        for (int i = tid; i < 1600; i += 128) {
            int c = i / 25, qq = i - c*25;
            float4 v4 = xg[(n*64 + c)*1600 + tile*25 + qq];
            int j = qq*4;
            float vals[4] = {v4.x, v4.y, v4.z, v4.w};
            #pragma unroll
            for (int k = 0; k < 4; ++k) {
                int tt = (j+k) / 25, v = (j+k) - tt*25;
                Xs[c*112 + tt*28 + v] = vals[k];
            }
        }
    }

    ull Y0[14], Y1[14];
    #pragma unroll
    for (int k = 0; k < 14; ++k) { Y0[k] = 0ULL; Y1[k] = 0ULL; }

    for (int s = 0; s < SS; ++s) {
        __syncthreads();
        for (int i = tid; i < 625; i += 128) Ais[(i/25)*28 + (i%25)] = g_Ai[(n*SS + s)*625 + i];
        for (int i = tid; i < 4096; i += 128) {
            int oo = i >> 6, c = i & 63;
            Wds[c*65 + oo] = Wd[s*4096 + i];
        }
        __syncthreads();

        ull U0[14], U1[14];
        #pragma unroll
        for (int k = 0; k < 14; ++k) { U0[k] = 0ULL; U1[k] = 0ULL; }
        {
            const float* xb = Xs + t*28;
            #pragma unroll 2
            for (int c = 0; c < 64; ++c) {
                ull w0 = pack2(Wds[c*65 + o0]);
                ull w1 = pack2(Wds[c*65 + o1]);
                const ulonglong2* xp = (const ulonglong2*)(xb + c*112);
                #pragma unroll
                for (int w4 = 0; w4 < 7; ++w4) {
                    ulonglong2 xv = xp[w4];
                    fma2(U0[2*w4], w0, xv.x); fma2(U0[2*w4+1], w0, xv.y);
                    fma2(U1[2*w4], w1, xv.x); fma2(U1[2*w4+1], w1, xv.y);
                }
            }
        }

        #pragma unroll
        for (int v = 0; v < 25; ++v) {
            float2 fu0 = unpack2(U0[v >> 1]);
            float2 fu1 = unpack2(U1[v >> 1]);
            ull uv0 = pack2((v & 1) ? fu0.y : fu0.x);
            ull uv1 = pack2((v & 1) ? fu1.y : fu1.x);
            const ulonglong2* ap = (const ulonglong2*)(Ais + v*28);
            #pragma unroll
            for (int w4 = 0; w4 < 7; ++w4) {
                ulonglong2 av = ap[w4];
                fma2(Y0[2*w4], uv0, av.x); fma2(Y0[2*w4+1], uv0, av.y);
                fma2(Y1[2*w4], uv1, av.x); fma2(Y1[2*w4+1], uv1, av.y);
            }
        }
    }

    float ya[28], yb[28];
    #pragma unroll
    for (int k = 0; k < 14; ++k) {
        float2 f0 = unpack2(Y0[k]); ya[2*k] = f0.x; ya[2*k+1] = f0.y;
        float2 f1 = unpack2(Y1[k]); yb[2*k] = f1.x; yb[2*k+1] = f1.y;
    }
    {
        const float scl  = rsqrtf(1.0f + 1e-5f);
        const float bsA = bd[o0] + bd[64+o0] + bd[128+o0];
        const float bsB = bd[o1] + bd[64+o1] + bd[128+o1];
        const float scA = gamma[o0]*scl, scB = gamma[o1]*scl;
        const float btA = beta[o0],      btB = beta[o1];
        const float* xrA = Xs + o0*112 + t*28;
        const float* xrB = Xs + o1*112 + t*28;
        #pragma unroll
        for (int w = 0; w < 25; ++w) {
            ya[w] = fmaxf((ya[w] + bsA)*scA + btA + xrA[w], 0.f);
            yb[w] = fmaxf((yb[w] + bsB)*scB + btB + xrB[w], 0.f);
        }
    }
    __syncthreads();
    #pragma unroll
    for (int w = 0; w < 25; ++w) {
        Xs[o0*100 + t*25 + w] = ya[w];
        Xs[o1*100 + t*25 + w] = yb[w];
    }
    __syncthreads();

    {
        float4* yg = (float4*)g_y0;
        const float4* Xs4 = (const float4*)Xs;
        for (int i = tid; i < 1600; i += 128) {
            int c = i / 25, qq = i - c*25;
            yg[(n*64 + c)*1600 + tile*25 + qq] = Xs4[c*25 + qq];
        }
        for (int i = tid; i < 1600; i += 128) {
            int c = i / 25, v = i - c*25;
            float ssum = Xs[c*100 + v] + Xs[c*100 + 25 + v]
                       + Xs[c*100 + 50 + v] + Xs[c*100 + 75 + v];
            atomicAdd(&g_ST[n*1600 + i], ssum);
        }
    }
}

// ---------------- K4: spatial gate ----------------
__global__ __launch_bounds__(128) void k4_sgate(const float* __restrict__ Wsa,
                                                const float* __restrict__ bsa)
{
    __shared__ float se[1600];
    __shared__ float wk[1600];
    const int tid = threadIdx.x, n = blockIdx.x;
    for (int i = tid; i < 1600; i += 128) {
        se[i] = g_ST[n*1600 + i] * (1.0f/256.0f);
        wk[i] = Wsa[i];
    }
    __syncthreads();
    if (tid < VV) {
        int v = tid;
        float acc = bsa[0];
        for (int c = 0; c < 64; ++c)
            #pragma unroll
            for (int k = 0; k < 25; ++k) {
                int u = v + k - 12;
                if (u >= 0 && u < 25) acc += wk[c*25 + k] * se[c*25 + u];
            }
        g_gs[n*25 + v] = 1.0f + sigm(acc);
    }
}

// ---------------- K5: SVw = sum_v y0*(1+gs) ----------------
__global__ __launch_bounds__(256) void k5_svw() {
    __shared__ float gs[25];
    const int c = blockIdx.x, n = blockIdx.y, t = threadIdx.x;
    if (t < 25) gs[t] = g_gs[n*25 + t];
    __syncthreads();
    const float* row = &g_y0[((n*64 + c)*256 + t)*25];
    float s = 0.f;
    #pragma unroll
    for (int v = 0; v < 25; ++v) s += row[v] * gs[v];
    g_SVw[(n*64 + c)*256 + t] = s;
}

// ---------------- K6: temporal gate ----------------
__global__ __launch_bounds__(256) void k6_tgate(const float* __restrict__ Wta,
                                                const float* __restrict__ bta)
{
    __shared__ float wk[576];
    const int tid = threadIdx.x, n = blockIdx.x;
    for (int i = tid; i < 576; i += 256) wk[i] = Wta[i];
    __syncthreads();
    const int t = tid;
    float s = 0.f;
    for (int c = 0; c < 64; ++c) {
        const float* sv = &g_SVw[(n*64 + c)*256];
        #pragma unroll
        for (int k = 0; k < 9; ++k) {
            int u = t + k - 4;
            if (u >= 0 && u < 256) s += wk[c*9 + k] * sv[u];
        }
    }
    float acc = bta[0] + s * (1.0f/25.0f);
    g_gt[n*256 + t] = 1.0f + sigm(acc);
}

// ---------------- K7: channel gate ----------------
__global__ __launch_bounds__(64) void k7_cgate(
    const float* __restrict__ W1, const float* __restrict__ b1,
    const float* __restrict__ W2, const float* __restrict__ b2)
{
    __shared__ float gt[256];
    __shared__ float se[64];
    __shared__ float h[32];
    const int tid = threadIdx.x, n = blockIdx.x;
    for (int i = tid; i < 256; i += 64) gt[i] = g_gt[n*256 + i];
    __syncthreads();
    {
        const float* sv = &g_SVw[(n*64 + tid)*256];
        float s = 0.f;
        for (int t = 0; t < 256; ++t) s += sv[t] * gt[t];
        se[tid] = s * (1.0f/6400.0f);
    }
    __syncthreads();
    if (tid < 32) {
        float a = b1[tid];
        for (int c = 0; c < 64; ++c) a += W1[tid*64 + c] * se[c];
        h[tid] = fmaxf(a, 0.f);
    }
    __syncthreads();
    {
        float a = b2[tid];
        #pragma unroll
        for (int j = 0; j < 32; ++j) a += W2[tid*32 + j] * h[j];
        g_gc[n*64 + tid] = 1.0f + sigm(a);
    }
}

// ---------------- K8: finalize ----------------
__global__ __launch_bounds__(256) void k8_final(float* __restrict__ out) {
    const int i4 = blockIdx.x*256 + threadIdx.x;
    if (i4 >= NB*CC*TT*VV/4) return;
    float4 y = ((const float4*)g_y0)[i4];
    float r[4] = {y.x, y.y, y.z, y.w};
    #pragma unroll
    for (int k = 0; k < 4; ++k) {
        unsigned idx = (unsigned)i4*4u + k;
        unsigned row = idx / 25u;
        unsigned v   = idx - row*25u;
        unsigned t   = row & 255u;
        unsigned nc  = row >> 8;
        unsigned n   = nc >> 6;
        r[k] *= g_gs[n*25 + v] * g_gt[n*256 + t] * g_gc[nc];
    }
    ((float4*)out)[i4] = make_float4(r[0], r[1], r[2], r[3]);
}

// ---------------- launch ----------------
extern "C" void kernel_launch(void* const* d_in, const int* in_sizes, int n_in,
                              void* d_out, int out_size) {
    const float* x     = (const float*)d_in[0];
    const float* PA    = (const float*)d_in[1];
    const float* alpha = (const float*)d_in[2];
    const float* Wa    = (const float*)d_in[3];
    const float* ba    = (const float*)d_in[4];
    const float* Wb    = (const float*)d_in[5];
    const float* bb    = (const float*)d_in[6];
    const float* Wd    = (const float*)d_in[7];
    const float* bd    = (const float*)d_in[8];
    const float* gam   = (const float*)d_in[9];
    const float* bet   = (const float*)d_in[10];
    const float* Wsa   = (const float*)d_in[11];
    const float* bsa   = (const float*)d_in[12];
    const float* Wta   = (const float*)d_in[13];
    const float* bta   = (const float*)d_in[14];
    const float* W1    = (const float*)d_in[15];
    const float* b1    = (const float*)d_in[16];
    const float* W2    = (const float*)d_in[17];
    const float* b2    = (const float*)d_in[18];
    float* out = (float*)d_out;

    cudaFuncSetAttribute(k1_emb_adj, cudaFuncAttributeMaxDynamicSharedMemorySize, 100352);
    cudaFuncSetAttribute(k3_main,    cudaFuncAttributeMaxDynamicSharedMemorySize, 49152);

    k0_zero<<<224, 1024>>>();
    k1_emb_adj<<<dim3(8, 64), 256, 99712>>>(x, Wa, ba, Wb, bb);
    k2_adj<<<120, 1024>>>(PA, alpha);
    k3_main<<<dim3(64, 64), 128, 48128>>>(x, Wd, bd, gam, bet);
    k4_sgate<<<64, 128>>>(Wsa, bsa);
    k5_svw<<<dim3(64, 64), 256>>>();
    k6_tgate<<<64, 256>>>(Wta, bta);
    k7_cgate<<<64, 64>>>(W1, b1, W2, b2);
    k8_final<<<25600, 256>>>(out);
}

// round 15
// speedup vs baseline: 1.8456x; 1.0493x over previous
#include <cuda_runtime.h>
#include <math.h>

#define NB 64
#define CC 64
#define TT 256
#define VV 25
#define SS 3
#define II 16

typedef unsigned long long ull;

// ---------------- device scratch ----------------
__device__ float g_A1 [NB*SS*VV*VV];
__device__ float g_Ai [NB*SS*VV*VV];
__device__ float g_y0 [NB*CC*TT*VV];   // ~105MB
__device__ float g_ST [NB*CC*VV];
__device__ float g_SVw[NB*CC*TT];
__device__ float g_gs [NB*VV];
__device__ float g_gt [NB*TT];
__device__ float g_gc [NB*CC];

__device__ __forceinline__ float sigm(float x) { return 1.0f / (1.0f + expf(-x)); }

// packed fp32x2 helpers
__device__ __forceinline__ ull pack2(float f) {
    ull r;
    asm("mov.b64 %0, {%1, %1};" : "=l"(r) : "r"(__float_as_uint(f)));
    return r;
}
__device__ __forceinline__ void fma2(ull& d, ull a, ull b) {
    asm("fma.rn.f32x2 %0, %1, %2, %0;" : "+l"(d) : "l"(a), "l"(b));
}
__device__ __forceinline__ float2 unpack2(ull p) {
    unsigned lo, hi;
    asm("mov.b64 {%0, %1}, %2;" : "=r"(lo), "=r"(hi) : "l"(p));
    return make_float2(__uint_as_float(lo), __uint_as_float(hi));
}

// ---------------- K0 ----------------
__global__ void k0_zero() {
    const int tot = NB*SS*VV*VV + NB*CC*VV;
    for (int i = blockIdx.x*blockDim.x + threadIdx.x; i < tot; i += gridDim.x*blockDim.x) {
        if (i < NB*SS*VV*VV) g_A1[i] = 0.f;
        else                 g_ST[i - NB*SS*VV*VV] = 0.f;
    }
}

// ---------------- K1: embeddings + partial A1 — s-FUSED single pass ----------------
// grid (8, 64), 256 threads, dyn smem 99712 B
__global__ __launch_bounds__(256) void k1_emb_adj(
    const float* __restrict__ x,  const float* __restrict__ Wa, const float* __restrict__ ba,
    const float* __restrict__ Wb, const float* __restrict__ bb)
{
    extern __shared__ float sm1[];
    float* Xs  = sm1;             // 7168:  [c][112] padded (pads 0)
    float* Es  = sm1 + 7168;      // 10752: [96][112]
    float* Wt3 = sm1 + 17920;     // 6912:  [s][c][36-pad j]
    float* bs3 = sm1 + 24832;     // 96:    [s][32]

    const int tid = threadIdx.x;
    const int n   = blockIdx.y;

    for (int i = tid; i < 6144; i += 256) {
        int s = i >> 11, r = i & 2047, j = r >> 6, c = r & 63;
        float w = (j < 16) ? Wa[(s*16 + j)*64 + c] : Wb[(s*16 + (j-16))*64 + c];
        Wt3[(s*64 + c)*36 + j] = w;
    }
    if (tid < 96) {
        int s = tid / 32, j = tid % 32;
        bs3[tid] = (j < 16) ? ba[s*16 + j] : bb[s*16 + (j-16)];
    }
    for (int i = tid; i < 768; i += 256) {
        int c = i / 12, r = i - c*12, tt = r / 3, k = r - tt*3;
        Xs[c*112 + tt*28 + 25 + k] = 0.f;
    }

    ull accX[SS], accY2[SS];
    #pragma unroll
    for (int s = 0; s < SS; ++s) { accX[s] = 0ULL; accY2[s] = 0ULL; }
    const bool hasA = tid < 175;
    const int  vA = tid / 7, w4A = tid % 7;

    const bool hasE = tid < 224;
    const int  jg = tid / 28, xo = tid % 28;

    __syncthreads();

    for (int sub = 0; sub < 8; ++sub) {
        const int tile = blockIdx.x * 8 + sub;
        __syncthreads();
        {
            const float4* xg = (const float4*)x;
            for (int i = tid; i < 1600; i += 256) {
                int c = i / 25, qq = i - c*25;
                float4 v4 = xg[(n*64 + c)*1600 + tile*25 + qq];
                int j = qq*4;
                float vals[4] = {v4.x, v4.y, v4.z, v4.w};
                #pragma unroll
                for (int k = 0; k < 4; ++k) {
                    int tt = (j+k) / 25, v = (j+k) - tt*25;
                    Xs[c*112 + tt*28 + v] = vals[k];
                }
            }
        }
        __syncthreads();

        if (hasE) {
            ull acc[SS][8];
            #pragma unroll
            for (int s = 0; s < SS; ++s) {
                const float* bsp = bs3 + s*32 + jg*4;
                #pragma unroll
                for (int k = 0; k < 4; ++k) {
                    ull b = pack2(bsp[k]);
                    acc[s][2*k] = b; acc[s][2*k+1] = b;
                }
            }
            const ulonglong2* Xs2 = (const ulonglong2*)Xs;
            #pragma unroll 8
            for (int c = 0; c < 64; ++c) {
                ulonglong2 xv = Xs2[c*28 + xo];
                #pragma unroll
                for (int s = 0; s < SS; ++s) {
                    float4 wv = *(const float4*)(Wt3 + (s*64 + c)*36 + jg*4);
                    ull w0 = pack2(wv.x), w1 = pack2(wv.y), w2 = pack2(wv.z), w3 = pack2(wv.w);
                    fma2(acc[s][0], w0, xv.x); fma2(acc[s][1], w0, xv.y);
                    fma2(acc[s][2], w1, xv.x); fma2(acc[s][3], w1, xv.y);
                    fma2(acc[s][4], w2, xv.x); fma2(acc[s][5], w2, xv.y);
                    fma2(acc[s][6], w3, xv.x); fma2(acc[s][7], w3, xv.y);
                }
            }
            ulonglong2* Es2 = (ulonglong2*)Es;
            #pragma unroll
            for (int s = 0; s < SS; ++s) {
                #pragma unroll
                for (int k = 0; k < 4; ++k)
                    Es2[(s*32 + jg*4 + k)*28 + xo] = make_ulonglong2(acc[s][2*k], acc[s][2*k+1]);
            }
        }
        __syncthreads();

        if (hasA) {
            #pragma unroll
            for (int s = 0; s < SS; ++s) {
                ull cx = accX[s], cy = accY2[s];
                const float* Ea = Es + (s*32)*112;
                const ulonglong2* Eb = (const ulonglong2*)(Es + (s*32 + 16)*112);
                #pragma unroll 8
                for (int j = 0; j < 16; ++j) {
                    #pragma unroll
                    for (int t = 0; t < 4; ++t) {
                        ull av = pack2(Ea[j*112 + t*28 + vA]);
                        ulonglong2 br = Eb[j*28 + t*7 + w4A];
                        fma2(cx, av, br.x); fma2(cy, av, br.y);
                    }
                }
                accX[s] = cx; accY2[s] = cy;
            }
        }
    }

    if (hasA) {
        #pragma unroll
        for (int s = 0; s < SS; ++s) {
            float2 f0 = unpack2(accX[s]), f1 = unpack2(accY2[s]);
            float vals[4] = {f0.x, f0.y, f1.x, f1.y};
            float* dst = &g_A1[((n*SS + s)*VV + vA)*VV];
            #pragma unroll
            for (int k = 0; k < 4; ++k) {
                int w = w4A*4 + k;
                if (w < VV) atomicAdd(&dst[w], vals[k]);
            }
        }
    }
}

// ---------------- K2 ----------------
__global__ void k2_adj(const float* __restrict__ PA, const float* __restrict__ alpha) {
    const float al = alpha[0];
    const int tot = NB*SS*VV*VV;
    for (int i = blockIdx.x*blockDim.x + threadIdx.x; i < tot; i += gridDim.x*blockDim.x)
        g_Ai[i] = PA[i % (SS*VV*VV)] + al * tanhf(g_A1[i] * (1.0f/4096.0f));
}

// ---------------- K3: fused (Wd@X)@Ai — o-PAIR per thread ----------------
// grid (64, 64), 128 threads, dyn smem 48128 B, 3 blocks/SM
__global__ __launch_bounds__(128, 3) void k3_main(
    const float* __restrict__ x,  const float* __restrict__ Wd, const float* __restrict__ bd,
    const float* __restrict__ gamma, const float* __restrict__ beta)
{
    extern __shared__ float sm[];
    float* Xs  = sm;            // 7168: [c][t*28+v] padded
    float* Ais = sm + 7168;     // 704:  [25][28] pad cols zeroed
    float* Wds = sm + 7872;     // 4160: [c][65-pad o]

    const int tid  = threadIdx.x;
    const int n    = blockIdx.y;
    const int tile = blockIdx.x;        // t0 = tile*4
    const int o0   = tid & 31;
    const int o1   = o0 + 32;
    const int t    = tid >> 5;          // one t per warp

    if (tid < 25) { Ais[tid*28+25] = 0.f; Ais[tid*28+26] = 0.f; Ais[tid*28+27] = 0.f; }
    for (int i = tid; i < 768; i += 128) {
        int c = i / 12, r = i - c*12, tt = r / 3, k = r - tt*3;
        Xs[c*112 + tt*28 + 25 + k] = 0.f;
    }
    {
        const float4* xg = (const float4*)x;
        for (int i = tid; i < 1600; i += 128) {
            int c = i / 25, qq = i - c*25;
            float4 v4 = xg[(n*64 + c)*1600 + tile*25 + qq];
            int j = qq*4;
            float vals[4] = {v4.x, v4.y, v4.z, v4.w};
            #pragma unroll
            for (int k = 0; k < 4; ++k) {
                int tt = (j+k) / 25, v = (j+k) - tt*25;
                Xs[c*112 + tt*28 + v] = vals[k];
            }
        }
    }

    ull Y0[14], Y1[14];
    #pragma unroll
    for (int k = 0; k < 14; ++k) { Y0[k] = 0ULL; Y1[k] = 0ULL; }

    for (int s = 0; s < SS; ++s) {
        __syncthreads();
        for (int i = tid; i < 625; i += 128) Ais[(i/25)*28 + (i%25)] = g_Ai[(n*SS + s)*625 + i];
        for (int i = tid; i < 4096; i += 128) {
            int oo = i >> 6, c = i & 63;
            Wds[c*65 + oo] = Wd[s*4096 + i];
        }
        __syncthreads();

        ull U0[14], U1[14];
        #pragma unroll
        for (int k = 0; k < 14; ++k) { U0[k] = 0ULL; U1[k] = 0ULL; }
        {
            const float* xb = Xs + t*28;
            #pragma unroll 8
            for (int c = 0; c < 64; ++c) {
                ull w0 = pack2(Wds[c*65 + o0]);
                ull w1 = pack2(Wds[c*65 + o1]);
                const ulonglong2* xp = (const ulonglong2*)(xb + c*112);
                #pragma unroll
                for (int w4 = 0; w4 < 7; ++w4) {
                    ulonglong2 xv = xp[w4];
                    fma2(U0[2*w4], w0, xv.x); fma2(U0[2*w4+1], w0, xv.y);
                    fma2(U1[2*w4], w1, xv.x); fma2(U1[2*w4+1], w1, xv.y);
                }
            }
        }

        #pragma unroll
        for (int v = 0; v < 25; ++v) {
            float2 fu0 = unpack2(U0[v >> 1]);
            float2 fu1 = unpack2(U1[v >> 1]);
            ull uv0 = pack2((v & 1) ? fu0.y : fu0.x);
            ull uv1 = pack2((v & 1) ? fu1.y : fu1.x);
            const ulonglong2* ap = (const ulonglong2*)(Ais + v*28);
            #pragma unroll
            for (int w4 = 0; w4 < 7; ++w4) {
                ulonglong2 av = ap[w4];
                fma2(Y0[2*w4], uv0, av.x); fma2(Y0[2*w4+1], uv0, av.y);
                fma2(Y1[2*w4], uv1, av.x); fma2(Y1[2*w4+1], uv1, av.y);
            }
        }
    }

    float ya[28], yb[28];
    #pragma unroll
    for (int k = 0; k < 14; ++k) {
        float2 f0 = unpack2(Y0[k]); ya[2*k] = f0.x; ya[2*k+1] = f0.y;
        float2 f1 = unpack2(Y1[k]); yb[2*k] = f1.x; yb[2*k+1] = f1.y;
    }
    {
        const float scl  = rsqrtf(1.0f + 1e-5f);
        const float bsA = bd[o0] + bd[64+o0] + bd[128+o0];
        const float bsB = bd[o1] + bd[64+o1] + bd[128+o1];
        const float scA = gamma[o0]*scl, scB = gamma[o1]*scl;
        const float btA = beta[o0],      btB = beta[o1];
        const float* xrA = Xs + o0*112 + t*28;
        const float* xrB = Xs + o1*112 + t*28;
        #pragma unroll
        for (int w = 0; w < 25; ++w) {
            ya[w] = fmaxf((ya[w] + bsA)*scA + btA + xrA[w], 0.f);
            yb[w] = fmaxf((yb[w] + bsB)*scB + btB + xrB[w], 0.f);
        }
    }
    __syncthreads();
    #pragma unroll
    for (int w = 0; w < 25; ++w) {
        Xs[o0*100 + t*25 + w] = ya[w];
        Xs[o1*100 + t*25 + w] = yb[w];
    }
    __syncthreads();

    {
        float4* yg = (float4*)g_y0;
        const float4* Xs4 = (const float4*)Xs;
        for (int i = tid; i < 1600; i += 128) {
            int c = i / 25, qq = i - c*25;
            yg[(n*64 + c)*1600 + tile*25 + qq] = Xs4[c*25 + qq];
        }
        for (int i = tid; i < 1600; i += 128) {
            int c = i / 25, v = i - c*25;
            float ssum = Xs[c*100 + v] + Xs[c*100 + 25 + v]
                       + Xs[c*100 + 50 + v] + Xs[c*100 + 75 + v];
            atomicAdd(&g_ST[n*1600 + i], ssum);
        }
    }
}

// ---------------- K4: spatial gate ----------------
__global__ __launch_bounds__(128) void k4_sgate(const float* __restrict__ Wsa,
                                                const float* __restrict__ bsa)
{
    __shared__ float se[1600];
    __shared__ float wk[1600];
    const int tid = threadIdx.x, n = blockIdx.x;
    for (int i = tid; i < 1600; i += 128) {
        se[i] = g_ST[n*1600 + i] * (1.0f/256.0f);
        wk[i] = Wsa[i];
    }
    __syncthreads();
    if (tid < VV) {
        int v = tid;
        float acc = bsa[0];
        for (int c = 0; c < 64; ++c)
            #pragma unroll
            for (int k = 0; k < 25; ++k) {
                int u = v + k - 12;
                if (u >= 0 && u < 25) acc += wk[c*25 + k] * se[c*25 + u];
            }
        g_gs[n*25 + v] = 1.0f + sigm(acc);
    }
}

// ---------------- K5: SVw = sum_v y0*(1+gs) — coalesced smem staging ----------------
// grid 4096 (n = bid>>6, c = bid&63), 256 threads, smem 25.7KB
__global__ __launch_bounds__(256) void k5_svw() {
    __shared__ float gs[25];
    __shared__ __align__(16) float ys[6400];
    const int bid = blockIdx.x;
    const int n = bid >> 6, c = bid & 63;
    const int tid = threadIdx.x;
    if (tid < 25) gs[tid] = g_gs[n*25 + tid];
    {   // coalesced float4 stage of the whole (n,c) slab
        const float4* yg = ((const float4*)g_y0) + (n*64 + c)*1600;
        float4* ys4 = (float4*)ys;
        for (int i = tid; i < 1600; i += 256) ys4[i] = yg[i];
    }
    __syncthreads();
    // per-thread dot from smem; stride 25 floats -> 25 % 32 banks, conflict-free
    const float* row = ys + tid*25;
    float s = 0.f;
    #pragma unroll
    for (int v = 0; v < 25; ++v) s += row[v] * gs[v];
    g_SVw[(n*64 + c)*256 + tid] = s;
}

// ---------------- K6: temporal gate ----------------
__global__ __launch_bounds__(256) void k6_tgate(const float* __restrict__ Wta,
                                                const float* __restrict__ bta)
{
    __shared__ float wk[576];
    const int tid = threadIdx.x, n = blockIdx.x;
    for (int i = tid; i < 576; i += 256) wk[i] = Wta[i];
    __syncthreads();
    const int t = tid;
    float s = 0.f;
    for (int c = 0; c < 64; ++c) {
        const float* sv = &g_SVw[(n*64 + c)*256];
        #pragma unroll
        for (int k = 0; k < 9; ++k) {
            int u = t + k - 4;
            if (u >= 0 && u < 256) s += wk[c*9 + k] * sv[u];
        }
    }
    float acc = bta[0] + s * (1.0f/25.0f);
    g_gt[n*256 + t] = 1.0f + sigm(acc);
}

// ---------------- K7: channel gate ----------------
__global__ __launch_bounds__(64) void k7_cgate(
    const float* __restrict__ W1, const float* __restrict__ b1,
    const float* __restrict__ W2, const float* __restrict__ b2)
{
    __shared__ float gt[256];
    __shared__ float se[64];
    __shared__ float h[32];
    const int tid = threadIdx.x, n = blockIdx.x;
    for (int i = tid; i < 256; i += 64) gt[i] = g_gt[n*256 + i];
    __syncthreads();
    {
        const float* sv = &g_SVw[(n*64 + tid)*256];
        float s = 0.f;
        for (int t = 0; t < 256; ++t) s += sv[t] * gt[t];
        se[tid] = s * (1.0f/6400.0f);
    }
    __syncthreads();
    if (tid < 32) {
        float a = b1[tid];
        for (int c = 0; c < 64; ++c) a += W1[tid*64 + c] * se[c];
        h[tid] = fmaxf(a, 0.f);
    }
    __syncthreads();
    {
        float a = b2[tid];
        #pragma unroll
        for (int j = 0; j < 32; ++j) a += W2[tid*32 + j] * h[j];
        g_gc[n*64 + tid] = 1.0f + sigm(a);
    }
}

// ---------------- K8: finalize ----------------
__global__ __launch_bounds__(256) void k8_final(float* __restrict__ out) {
    const int i4 = blockIdx.x*256 + threadIdx.x;
    if (i4 >= NB*CC*TT*VV/4) return;
    float4 y = ((const float4*)g_y0)[i4];
    float r[4] = {y.x, y.y, y.z, y.w};
    #pragma unroll
    for (int k = 0; k < 4; ++k) {
        unsigned idx = (unsigned)i4*4u + k;
        unsigned row = idx / 25u;
        unsigned v   = idx - row*25u;
        unsigned t   = row & 255u;
        unsigned nc  = row >> 8;
        unsigned n   = nc >> 6;
        r[k] *= g_gs[n*25 + v] * g_gt[n*256 + t] * g_gc[nc];
    }
    ((float4*)out)[i4] = make_float4(r[0], r[1], r[2], r[3]);
}

// ---------------- launch ----------------
extern "C" void kernel_launch(void* const* d_in, const int* in_sizes, int n_in,
                              void* d_out, int out_size) {
    const float* x     = (const float*)d_in[0];
    const float* PA    = (const float*)d_in[1];
    const float* alpha = (const float*)d_in[2];
    const float* Wa    = (const float*)d_in[3];
    const float* ba    = (const float*)d_in[4];
    const float* Wb    = (const float*)d_in[5];
    const float* bb    = (const float*)d_in[6];
    const float* Wd    = (const float*)d_in[7];
    const float* bd    = (const float*)d_in[8];
    const float* gam   = (const float*)d_in[9];
    const float* bet   = (const float*)d_in[10];
    const float* Wsa   = (const float*)d_in[11];
    const float* bsa   = (const float*)d_in[12];
    const float* Wta   = (const float*)d_in[13];
    const float* bta   = (const float*)d_in[14];
    const float* W1    = (const float*)d_in[15];
    const float* b1    = (const float*)d_in[16];
    const float* W2    = (const float*)d_in[17];
    const float* b2    = (const float*)d_in[18];
    float* out = (float*)d_out;

    cudaFuncSetAttribute(k1_emb_adj, cudaFuncAttributeMaxDynamicSharedMemorySize, 100352);
    cudaFuncSetAttribute(k3_main,    cudaFuncAttributeMaxDynamicSharedMemorySize, 49152);

    k0_zero<<<224, 1024>>>();
    k1_emb_adj<<<dim3(8, 64), 256, 99712>>>(x, Wa, ba, Wb, bb);
    k2_adj<<<120, 1024>>>(PA, alpha);
    k3_main<<<dim3(64, 64), 128, 48128>>>(x, Wd, bd, gam, bet);
    k4_sgate<<<64, 128>>>(Wsa, bsa);
    k5_svw<<<4096, 256>>>();
    k6_tgate<<<64, 256>>>(Wta, bta);
    k7_cgate<<<64, 64>>>(W1, b1, W2, b2);
    k8_final<<<25600, 256>>>(out);
}